// round 5
// baseline (speedup 1.0000x reference)
#include <cuda_runtime.h>
#include <math.h>

#define B_   8
#define N_   1024
#define C_   768
#define H_   12
#define HID_ 3072
#define RN_  513
#define MROWS (B_*RN_)   // 4104

// ---------------- scratch (static __device__, no allocation) ----------------
__device__ float g_XN  [B_*N_*C_];        // 25 MB
__device__ float g_QKV [B_*N_*3*C_];      // 75 MB
__device__ float g_XATT[B_*N_*C_];        // 25 MB
__device__ float g_CLSH[B_*H_*(N_-1)];    // per-head attention row 0 (cols 1..1023)
__device__ int   g_ROWSEL[B_*RN_];        // selected global rows (b*1024+n)
__device__ float g_XP  [MROWS*C_];        // x_gathered + proj (pre-MLP residual)
__device__ float g_XN2 [MROWS*C_];
__device__ float g_HB  [MROWS*HID_];

__device__ __forceinline__ float gelu_exact(float v) {
    return 0.5f * v * (1.0f + erff(v * 0.70710678118654752f));
}

// ---------------- LayerNorm (1 row / block, C=768, 256 threads) -------------
__global__ __launch_bounds__(256) void ln_kernel(
    const float* __restrict__ X, const float* __restrict__ g,
    const float* __restrict__ bt, float* __restrict__ Y)
{
    __shared__ float red[8];
    int row = blockIdx.x, t = threadIdx.x;
    const float* xr = X + (size_t)row * C_;
    float x0 = xr[t], x1 = xr[t+256], x2 = xr[t+512];
    float s = x0 + x1 + x2;
    #pragma unroll
    for (int o = 16; o; o >>= 1) s += __shfl_xor_sync(~0u, s, o);
    if ((t & 31) == 0) red[t >> 5] = s;
    __syncthreads();
    float tot = 0.f;
    #pragma unroll
    for (int i = 0; i < 8; i++) tot += red[i];
    float mean = tot * (1.0f/768.0f);
    __syncthreads();
    float d0 = x0-mean, d1 = x1-mean, d2 = x2-mean;
    float q = d0*d0 + d1*d1 + d2*d2;
    #pragma unroll
    for (int o = 16; o; o >>= 1) q += __shfl_xor_sync(~0u, q, o);
    if ((t & 31) == 0) red[t >> 5] = q;
    __syncthreads();
    float tq = 0.f;
    #pragma unroll
    for (int i = 0; i < 8; i++) tq += red[i];
    float rstd = 1.0f / sqrtf(tq * (1.0f/768.0f) + 1e-5f);
    float* yr = Y + (size_t)row * C_;
    yr[t]     = d0*rstd*g[t]     + bt[t];
    yr[t+256] = d1*rstd*g[t+256] + bt[t+256];
    yr[t+512] = d2*rstd*g[t+512] + bt[t+512];
}

// ---------------- SGEMM: 128x128x8 tiles, 8x8 microtile, 256 threads --------
// EPI: 0 = plain store, 1 = +bias +residual, 2 = +bias, GELU
template<bool GATHER, int EPI>
__global__ __launch_bounds__(256) void sgemm_kernel(
    const float* __restrict__ A, const float* __restrict__ Bm, float* __restrict__ Cm,
    int M, int N, int K,
    const float* __restrict__ bias, const float* __restrict__ resid,
    const int* __restrict__ rowmap)
{
    __shared__ float As[8][128];
    __shared__ float Bs[8][128];
    int t = threadIdx.x;
    int row0 = blockIdx.y * 128, col0 = blockIdx.x * 128;

    int la_r = t >> 1, la_k = (t & 1) * 4;
    long a_base = -1;
    {
        int arow = row0 + la_r;
        if (arow < M) {
            int gr = GATHER ? rowmap[arow] : arow;
            a_base = (long)gr * K;
        }
    }
    int lb_k = t >> 5, lb_c = (t & 31) * 4;
    const float* bp = Bm + (size_t)lb_k * N + col0 + lb_c;

    int ty = t >> 4, tx = t & 15;
    float acc[8][8] = {{0.f}};

    float4 av = make_float4(0.f,0.f,0.f,0.f), bv;
    if (a_base >= 0) av = *(const float4*)(A + a_base + la_k);
    bv = *(const float4*)bp;

    for (int k0 = 0; k0 < K; k0 += 8) {
        __syncthreads();
        As[la_k  ][la_r] = av.x;  As[la_k+1][la_r] = av.y;
        As[la_k+2][la_r] = av.z;  As[la_k+3][la_r] = av.w;
        *(float4*)&Bs[lb_k][lb_c] = bv;
        __syncthreads();
        if (k0 + 8 < K) {
            if (a_base >= 0) av = *(const float4*)(A + a_base + k0 + 8 + la_k);
            bv = *(const float4*)(bp + (size_t)(k0 + 8) * N);
        }
        #pragma unroll
        for (int kk = 0; kk < 8; kk++) {
            float4 a0 = *(const float4*)&As[kk][ty*8];
            float4 a1 = *(const float4*)&As[kk][ty*8+4];
            float4 b0 = *(const float4*)&Bs[kk][tx*8];
            float4 b1 = *(const float4*)&Bs[kk][tx*8+4];
            float ar[8] = {a0.x,a0.y,a0.z,a0.w,a1.x,a1.y,a1.z,a1.w};
            float br[8] = {b0.x,b0.y,b0.z,b0.w,b1.x,b1.y,b1.z,b1.w};
            #pragma unroll
            for (int i = 0; i < 8; i++)
                #pragma unroll
                for (int j = 0; j < 8; j++)
                    acc[i][j] = fmaf(ar[i], br[j], acc[i][j]);
        }
    }

    #pragma unroll
    for (int i = 0; i < 8; i++) {
        int row = row0 + ty*8 + i;
        if (row < M) {
            long rres = 0;
            if (EPI == 1) {
                int gr = GATHER ? rowmap[row] : row;
                rres = (long)gr * N;
            }
            #pragma unroll
            for (int jj = 0; jj < 8; jj += 4) {
                int col = col0 + tx*8 + jj;
                float4 v = make_float4(acc[i][jj], acc[i][jj+1], acc[i][jj+2], acc[i][jj+3]);
                if (EPI != 0) {
                    float4 bb = *(const float4*)&bias[col];
                    v.x += bb.x; v.y += bb.y; v.z += bb.z; v.w += bb.w;
                }
                if (EPI == 2) {
                    v.x = gelu_exact(v.x); v.y = gelu_exact(v.y);
                    v.z = gelu_exact(v.z); v.w = gelu_exact(v.w);
                }
                if (EPI == 1) {
                    float4 rv = *(const float4*)&resid[rres + col];
                    v.x += rv.x; v.y += rv.y; v.z += rv.z; v.w += rv.w;
                }
                *(float4*)&Cm[(size_t)row * N + col] = v;
            }
        }
    }
}

// ---------------- Attention: block = (32-row tile, head, batch) -------------
// scores (32x1024) resident in smem; softmax per warp-row; AV accumulate.
// Writes XATT[b,n,h*64+d] and, for n==0 rows, the per-head cls row to CLSH.
__global__ __launch_bounds__(256) void attn_kernel(
    const float* __restrict__ QKV, const float* __restrict__ amask,
    float* __restrict__ XATT, float* __restrict__ CLSH)
{
    extern __shared__ float smx[];
    float* sS  = smx;                 // 32*1024
    float* sQt = smx + 32*1024;       // [64][36]  Q transposed
    float* sT  = sQt + 64*36;         // 8448 floats: K^T [64][132] / V [128][66]
    int t = threadIdx.x;
    int n0 = blockIdx.x * 32, h = blockIdx.y, b = blockIdx.z;
    size_t base_bh = (size_t)b * N_ * 2304 + (size_t)h * 64;

    // Q tile -> sQt[d][i]
    for (int e = t; e < 32*64; e += 256) {
        int i = e >> 6, d = e & 63;
        sQt[d*36 + i] = QKV[base_bh + (size_t)(n0 + i) * 2304 + d];
    }

    int ty = t >> 5, tx = t & 31;

    // ---- scores: S = (Q K^T) * 0.125 ----
    for (int kt = 0; kt < 8; kt++) {
        int m0 = kt << 7;
        __syncthreads();
        for (int e = t; e < 128*64; e += 256) {
            int m = e >> 6, d = e & 63;
            sT[d*132 + m] = QKV[base_bh + 768 + (size_t)(m0 + m) * 2304 + d];
        }
        __syncthreads();
        float acc[4][4] = {{0.f}};
        #pragma unroll 4
        for (int d = 0; d < 64; d++) {
            float4 aq = *(const float4*)&sQt[d*36 + ty*4];
            float4 bk = *(const float4*)&sT[d*132 + tx*4];
            float ar[4] = {aq.x,aq.y,aq.z,aq.w};
            float br[4] = {bk.x,bk.y,bk.z,bk.w};
            #pragma unroll
            for (int i = 0; i < 4; i++)
                #pragma unroll
                for (int j = 0; j < 4; j++)
                    acc[i][j] = fmaf(ar[i], br[j], acc[i][j]);
        }
        #pragma unroll
        for (int i = 0; i < 4; i++) {
            float4 v = make_float4(acc[i][0]*0.125f, acc[i][1]*0.125f,
                                   acc[i][2]*0.125f, acc[i][3]*0.125f);
            *(float4*)&sS[(ty*4+i)*1024 + m0 + tx*4] = v;
        }
    }
    __syncthreads();

    // ---- softmax (jax variant): a = (exp(s-max)*mask + eps/N) / (sum + eps) ----
    int lane = t & 31, w = t >> 5;
    for (int rr = 0; rr < 4; rr++) {
        int i = w + rr*8;
        int n = n0 + i;
        float* row = sS + i*1024;
        float mx = -3.4e38f;
        for (int m = lane; m < 1024; m += 32) mx = fmaxf(mx, row[m]);
        #pragma unroll
        for (int o = 16; o; o >>= 1) mx = fmaxf(mx, __shfl_xor_sync(~0u, mx, o));
        const float* mrow = amask + (size_t)(b * N_ + n) * N_;
        float sum = 0.f;
        for (int m = lane; m < 1024; m += 32) {
            float e = expf(row[m] - mx) * mrow[m];
            row[m] = e;
            sum += e;
        }
        #pragma unroll
        for (int o = 16; o; o >>= 1) sum += __shfl_xor_sync(~0u, sum, o);
        float rinv = 1.0f / (sum + 1e-6f);
        const float epsn = 1e-6f / 1024.0f;
        for (int m = lane; m < 1024; m += 32) row[m] = (row[m] + epsn) * rinv;
        if (n == 0) {
            float* cl = CLSH + (size_t)(b * H_ + h) * (N_ - 1);
            for (int m = 1 + lane; m < 1024; m += 32) cl[m-1] = row[m];
        }
    }
    __syncthreads();

    // ---- AV: out[32][64] += A * V ----
    float oacc[4][2] = {{0.f}};
    for (int vt = 0; vt < 8; vt++) {
        int m0 = vt << 7;
        __syncthreads();
        for (int e = t; e < 128*64; e += 256) {
            int m = e >> 6, d = e & 63;
            sT[m*66 + d] = QKV[base_bh + 1536 + (size_t)(m0 + m) * 2304 + d];
        }
        __syncthreads();
        #pragma unroll 4
        for (int m = 0; m < 128; m++) {
            float2 vv = *(const float2*)&sT[m*66 + tx*2];
            #pragma unroll
            for (int i = 0; i < 4; i++) {
                float a = sS[(ty*4+i)*1024 + m0 + m];
                oacc[i][0] = fmaf(a, vv.x, oacc[i][0]);
                oacc[i][1] = fmaf(a, vv.y, oacc[i][1]);
            }
        }
    }
    #pragma unroll
    for (int i = 0; i < 4; i++) {
        int n = n0 + ty*4 + i;
        float2 o2 = make_float2(oacc[i][0], oacc[i][1]);
        *(float2*)&XATT[(size_t)(b * N_ + n) * C_ + h*64 + tx*2] = o2;
    }
}

// ---------------- top-k via bitonic sort (jax.lax.top_k semantics) ----------
// key: value desc, tie -> lower index first. block = (segment, batch).
__global__ __launch_bounds__(256) void topk_kernel(
    const float* __restrict__ CLSH, int* __restrict__ ROWSEL,
    float* __restrict__ outIA, float* __restrict__ outIM)
{
    __shared__ float sv[1024];
    __shared__ int   si[1024];
    int seg = blockIdx.x, b = blockIdx.y, t = threadIdx.x;
    int P     = seg ? 1024 : 256;
    int count = seg ? 768  : 255;
    int base  = seg ? 255  : 0;

    for (int e = t; e < P; e += 256) {
        if (e < count) {
            float s = 0.f;
            #pragma unroll
            for (int hh = 0; hh < 12; hh++)
                s += CLSH[(size_t)(b*12 + hh) * 1023 + base + e];
            sv[e] = s;        // /H omitted: monotonic, ordering identical
            si[e] = e;
        } else { sv[e] = -3.4e38f; si[e] = 0x7FFFFFFF; }
    }

    for (int k = 2; k <= P; k <<= 1)
        for (int j = k >> 1; j > 0; j >>= 1) {
            __syncthreads();
            for (int i = t; i < P; i += 256) {
                int ixj = i ^ j;
                if (ixj > i) {
                    float v1 = sv[i], v2 = sv[ixj];
                    int a1 = si[i], a2 = si[ixj];
                    bool before12 = (v1 > v2) || (v1 == v2 && a1 < a2);
                    bool up = ((i & k) == 0);
                    if (up != before12) {
                        sv[i] = v2; sv[ixj] = v1; si[i] = a2; si[ixj] = a1;
                    }
                }
            }
        }
    __syncthreads();

    if (seg == 0) {
        if (t < 128) {
            int idx = si[t];
            if (outIA) outIA[b*128 + t] = (float)idx;
            ROWSEL[b*513 + 1 + t] = b*1024 + 1 + idx;
        }
        if (t == 0) ROWSEL[b*513] = b*1024;   // cls row
    } else {
        for (int e = t; e < 384; e += 256) {
            int idx = si[e];
            if (outIM) outIM[b*384 + e] = (float)idx;
            ROWSEL[b*513 + 129 + e] = b*1024 + 256 + idx;
        }
    }
}

__global__ void fill_ones(float* __restrict__ p, int n) {
    int i = blockIdx.x * 256 + threadIdx.x;
    if (i < n) p[i] = 1.0f;
}

// ---------------- launcher ----------------
extern "C" void kernel_launch(void* const* d_in, const int* in_sizes, int n_in,
                              void* d_out, int out_size)
{
    const float* x      = (const float*)d_in[0];
    const float* amask  = (const float*)d_in[1];
    // d_in[2], d_in[3]: token_idx_* — shape-only in the reference, unused
    const float* w_qkv  = (const float*)d_in[4];
    const float* w_proj = (const float*)d_in[5];
    const float* b_proj = (const float*)d_in[6];
    const float* g1     = (const float*)d_in[7];
    const float* b1     = (const float*)d_in[8];
    const float* g2     = (const float*)d_in[9];
    const float* b2     = (const float*)d_in[10];
    const float* w_fc1  = (const float*)d_in[11];
    const float* b_fc1  = (const float*)d_in[12];
    const float* w_fc2  = (const float*)d_in[13];
    const float* b_fc2  = (const float*)d_in[14];
    float* out = (float*)d_out;

    float *XN, *QKV, *XATT, *CLSH, *XP, *XN2, *HB; int* ROWSEL;
    cudaGetSymbolAddress((void**)&XN,   g_XN);
    cudaGetSymbolAddress((void**)&QKV,  g_QKV);
    cudaGetSymbolAddress((void**)&XATT, g_XATT);
    cudaGetSymbolAddress((void**)&CLSH, g_CLSH);
    cudaGetSymbolAddress((void**)&XP,   g_XP);
    cudaGetSymbolAddress((void**)&XN2,  g_XN2);
    cudaGetSymbolAddress((void**)&HB,   g_HB);
    cudaGetSymbolAddress((void**)&ROWSEL, g_ROWSEL);

    const int ATTN_SMEM = (32*1024 + 64*36 + 8448) * 4;  // 174080 B
    cudaFuncSetAttribute(attn_kernel,
        cudaFuncAttributeMaxDynamicSharedMemorySize, ATTN_SMEM);

    // output layout: x[8,513,768] | idx_a[8,128] | idx_m[8,384] | new_mask[8,513,513]
    const int OFF_IA = 8*513*768;            // 3151872
    const int OFF_IM = OFF_IA + 8*128;       // 3152896
    const int OFF_MK = OFF_IM + 8*384;       // 3155968
    const int MK_SZ  = 8*513*513;            // 2105352
    const int TOTAL  = OFF_MK + MK_SZ;       // 5261320
    float* outIA = (out_size >= TOTAL) ? out + OFF_IA : nullptr;
    float* outIM = (out_size >= TOTAL) ? out + OFF_IM : nullptr;

    // 1. LN1
    ln_kernel<<<B_*N_, 256>>>(x, g1, b1, XN);
    // 2. QKV GEMM  [8192,768] @ [768,2304]
    sgemm_kernel<false,0><<<dim3(2304/128, 8192/128), 256>>>(
        XN, w_qkv, QKV, B_*N_, 3*C_, C_, nullptr, nullptr, nullptr);
    // 3. attention (writes XATT + per-head cls rows)
    attn_kernel<<<dim3(N_/32, H_, B_), 256, ATTN_SMEM>>>(QKV, amask, XATT, CLSH);
    // 4. top-k selection -> idx outputs + ROWSEL
    topk_kernel<<<dim3(2, B_), 256>>>(CLSH, ROWSEL, outIA, outIM);
    // 5. gathered proj: XP = x[sel] + (XATT[sel] @ w_proj + b_proj)
    sgemm_kernel<true,1><<<dim3(768/128, (MROWS+127)/128), 256>>>(
        XATT, w_proj, XP, MROWS, C_, C_, b_proj, x, ROWSEL);
    // 6. LN2
    ln_kernel<<<MROWS, 256>>>(XP, g2, b2, XN2);
    // 7. fc1 + GELU(exact)
    sgemm_kernel<false,2><<<dim3(3072/128, (MROWS+127)/128), 256>>>(
        XN2, w_fc1, HB, MROWS, HID_, C_, b_fc1, nullptr, nullptr);
    // 8. fc2 + bias + residual(XP) -> final x, directly into d_out
    sgemm_kernel<false,1><<<dim3(768/128, (MROWS+127)/128), 256>>>(
        HB, w_fc2, out, MROWS, C_, HID_, b_fc2, XP, nullptr);
    // 9. new_mask == all ones (proved: kAa/kAm equal gathered row lengths,
    //    so threshold is the row min and every comparison is true)
    if (out_size >= TOTAL)
        fill_ones<<<(MK_SZ + 255)/256, 256>>>(out + OFF_MK, MK_SZ);
}

// round 7
// speedup vs baseline: 1.0227x; 1.0227x over previous
#include <cuda_runtime.h>
#include <math.h>

#define B_   8
#define N_   1024
#define C_   768
#define H_   12
#define HID_ 3072
#define RN_  513
#define MROWS (B_*RN_)   // 4104

// ---------------- scratch (static __device__, no allocation) ----------------
__device__ float g_XN  [B_*N_*C_];
__device__ float g_QKV [B_*N_*3*C_];
__device__ float g_XATT[B_*N_*C_];
__device__ float g_CLSH[B_*H_*(N_-1)];
__device__ int   g_ROWSEL[B_*RN_];
__device__ float g_XP  [MROWS*C_];
__device__ float g_XN2 [MROWS*C_];
__device__ float g_HB  [MROWS*HID_];

__device__ __forceinline__ float gelu_exact(float v) {
    return 0.5f * v * (1.0f + erff(v * 0.70710678118654752f));
}

// split fp32 into two truncated-tf32 parts: v ~= hi + lo
__device__ __forceinline__ void splitf(float v, float& hi, float& lo) {
    unsigned uh = __float_as_uint(v) & 0xffffe000u;
    hi = __uint_as_float(uh);
    float l = v - hi;
    lo = __uint_as_float(__float_as_uint(l) & 0xffffe000u);
}

__device__ __forceinline__ void mma_tf32(float* c,
    unsigned a0, unsigned a1, unsigned a2, unsigned a3,
    unsigned b0, unsigned b1)
{
    asm volatile(
        "mma.sync.aligned.m16n8k8.row.col.f32.tf32.tf32.f32 "
        "{%0,%1,%2,%3},{%4,%5,%6,%7},{%8,%9},{%0,%1,%2,%3};"
        : "+f"(c[0]), "+f"(c[1]), "+f"(c[2]), "+f"(c[3])
        : "r"(a0), "r"(a1), "r"(a2), "r"(a3), "r"(b0), "r"(b1));
}

// ---------------- LayerNorm (1 row / block, C=768, 256 threads) -------------
__global__ __launch_bounds__(256) void ln_kernel(
    const float* __restrict__ X, const float* __restrict__ g,
    const float* __restrict__ bt, float* __restrict__ Y)
{
    __shared__ float red[8];
    int row = blockIdx.x, t = threadIdx.x;
    const float* xr = X + (size_t)row * C_;
    float x0 = xr[t], x1 = xr[t+256], x2 = xr[t+512];
    float s = x0 + x1 + x2;
    #pragma unroll
    for (int o = 16; o; o >>= 1) s += __shfl_xor_sync(~0u, s, o);
    if ((t & 31) == 0) red[t >> 5] = s;
    __syncthreads();
    float tot = 0.f;
    #pragma unroll
    for (int i = 0; i < 8; i++) tot += red[i];
    float mean = tot * (1.0f/768.0f);
    __syncthreads();
    float d0 = x0-mean, d1 = x1-mean, d2 = x2-mean;
    float q = d0*d0 + d1*d1 + d2*d2;
    #pragma unroll
    for (int o = 16; o; o >>= 1) q += __shfl_xor_sync(~0u, q, o);
    if ((t & 31) == 0) red[t >> 5] = q;
    __syncthreads();
    float tq = 0.f;
    #pragma unroll
    for (int i = 0; i < 8; i++) tq += red[i];
    float rstd = 1.0f / sqrtf(tq * (1.0f/768.0f) + 1e-5f);
    float* yr = Y + (size_t)row * C_;
    yr[t]     = d0*rstd*g[t]     + bt[t];
    yr[t+256] = d1*rstd*g[t+256] + bt[t+256];
    yr[t+512] = d2*rstd*g[t+512] + bt[t+512];
}

// ---------------- fp32 SGEMM (exact path for QKV): 128x128x8, 8x8 micro ----
__global__ __launch_bounds__(256) void sgemm_kernel(
    const float* __restrict__ A, const float* __restrict__ Bm, float* __restrict__ Cm,
    int M, int N, int K)
{
    __shared__ float As[8][128];
    __shared__ float Bs[8][128];
    int t = threadIdx.x;
    int row0 = blockIdx.y * 128, col0 = blockIdx.x * 128;

    int la_r = t >> 1, la_k = (t & 1) * 4;
    long a_base = -1;
    {
        int arow = row0 + la_r;
        if (arow < M) a_base = (long)arow * K;
    }
    int lb_k = t >> 5, lb_c = (t & 31) * 4;
    const float* bp = Bm + (size_t)lb_k * N + col0 + lb_c;

    int ty = t >> 4, tx = t & 15;
    float acc[8][8] = {{0.f}};

    float4 av = make_float4(0.f,0.f,0.f,0.f), bv;
    if (a_base >= 0) av = *(const float4*)(A + a_base + la_k);
    bv = *(const float4*)bp;

    for (int k0 = 0; k0 < K; k0 += 8) {
        __syncthreads();
        As[la_k  ][la_r] = av.x;  As[la_k+1][la_r] = av.y;
        As[la_k+2][la_r] = av.z;  As[la_k+3][la_r] = av.w;
        *(float4*)&Bs[lb_k][lb_c] = bv;
        __syncthreads();
        if (k0 + 8 < K) {
            if (a_base >= 0) av = *(const float4*)(A + a_base + k0 + 8 + la_k);
            bv = *(const float4*)(bp + (size_t)(k0 + 8) * N);
        }
        #pragma unroll
        for (int kk = 0; kk < 8; kk++) {
            float4 a0 = *(const float4*)&As[kk][ty*8];
            float4 a1 = *(const float4*)&As[kk][ty*8+4];
            float4 b0 = *(const float4*)&Bs[kk][tx*8];
            float4 b1 = *(const float4*)&Bs[kk][tx*8+4];
            float ar[8] = {a0.x,a0.y,a0.z,a0.w,a1.x,a1.y,a1.z,a1.w};
            float br[8] = {b0.x,b0.y,b0.z,b0.w,b1.x,b1.y,b1.z,b1.w};
            #pragma unroll
            for (int i = 0; i < 8; i++)
                #pragma unroll
                for (int j = 0; j < 8; j++)
                    acc[i][j] = fmaf(ar[i], br[j], acc[i][j]);
        }
    }

    #pragma unroll
    for (int i = 0; i < 8; i++) {
        int row = row0 + ty*8 + i;
        if (row < M) {
            #pragma unroll
            for (int jj = 0; jj < 8; jj += 4) {
                int col = col0 + tx*8 + jj;
                float4 v = make_float4(acc[i][jj], acc[i][jj+1], acc[i][jj+2], acc[i][jj+3]);
                *(float4*)&Cm[(size_t)row * N + col] = v;
            }
        }
    }
}

// ---------------- 3xTF32 MMA GEMM: 128x128 block, BK=16, 256 threads --------
// (downstream-of-topk GEMMs only: proj / fc1 / fc2 — 1e-3 tolerance path)
// EPI: 0 = plain store, 1 = +bias +residual, 2 = +bias, GELU
template<bool GATHER, int EPI>
__global__ __launch_bounds__(256) void mma_gemm(
    const float* __restrict__ A, const float* __restrict__ Bm, float* __restrict__ Cm,
    int M, int N, int K,
    const float* __restrict__ bias, const float* __restrict__ resid,
    const int* __restrict__ rowmap)
{
    extern __shared__ float sm[];
    float* sAh = sm;
    float* sAl = sm + 4352;
    float* sBh = sm + 8704;
    float* sBl = sm + 13056;

    const int t    = threadIdx.x;
    const int lane = t & 31, wid = t >> 5;
    const int lq = lane >> 2, lr = lane & 3;
    const int wm = wid & 1,  wn = wid >> 1;
    const int row0 = blockIdx.y * 128, col0 = blockIdx.x * 128;

    const int am = t & 127, ak0 = (t >> 7) * 8;
    long a_base = -1;
    {
        int arow = row0 + am;
        if (arow < M) a_base = (long)(GATHER ? rowmap[arow] : arow) * K;
    }
    const int bk = wid, bn = lane * 4;
    const float* bptr = Bm + (size_t)bk * N + col0 + bn;

    float acc[4][4][4];
    #pragma unroll
    for (int i = 0; i < 4; i++)
        #pragma unroll
        for (int j = 0; j < 4; j++)
            #pragma unroll
            for (int q = 0; q < 4; q++) acc[i][j][q] = 0.f;

    float4 aR0, aR1, bR0, bR1;

    auto ldg = [&](int kt) {
        if (a_base >= 0) {
            aR0 = *(const float4*)(A + a_base + kt*16 + ak0);
            aR1 = *(const float4*)(A + a_base + kt*16 + ak0 + 4);
        } else {
            aR0 = make_float4(0.f,0.f,0.f,0.f);
            aR1 = make_float4(0.f,0.f,0.f,0.f);
        }
        bR0 = *(const float4*)(bptr + (size_t)(kt*16) * N);
        bR1 = *(const float4*)(bptr + (size_t)(kt*16 + 8) * N);
    };
    auto sts = [&](int buf) {
        float va[8] = {aR0.x,aR0.y,aR0.z,aR0.w,aR1.x,aR1.y,aR1.z,aR1.w};
        int ab = buf*2176 + ak0*136 + am;
        #pragma unroll
        for (int j = 0; j < 8; j++) {
            float h, l; splitf(va[j], h, l);
            sAh[ab + j*136] = h;
            sAl[ab + j*136] = l;
        }
        float vb[8] = {bR0.x,bR0.y,bR0.z,bR0.w,bR1.x,bR1.y,bR1.z,bR1.w};
        float hb[8], lb[8];
        #pragma unroll
        for (int j = 0; j < 8; j++) splitf(vb[j], hb[j], lb[j]);
        int b0 = buf*2176 + bk*136 + bn;
        int b1 = b0 + 8*136;
        *(float4*)&sBh[b0] = make_float4(hb[0],hb[1],hb[2],hb[3]);
        *(float4*)&sBl[b0] = make_float4(lb[0],lb[1],lb[2],lb[3]);
        *(float4*)&sBh[b1] = make_float4(hb[4],hb[5],hb[6],hb[7]);
        *(float4*)&sBl[b1] = make_float4(lb[4],lb[5],lb[6],lb[7]);
    };

    const int KT = K >> 4;
    ldg(0);
    sts(0);
    __syncthreads();

    for (int kt = 0; kt < KT; ++kt) {
        const int buf = kt & 1;
        if (kt + 1 < KT) ldg(kt + 1);

        #pragma unroll
        for (int ks = 0; ks < 2; ks++) {
            const int krow = buf*2176 + (ks*8 + lr)*136;
            unsigned ah[4][4], al_[4][4], bh[4][2], bl_[4][2];
            #pragma unroll
            for (int mf = 0; mf < 4; mf++) {
                int m = wm*64 + mf*16 + lq;
                int p0 = krow + m, p4 = p0 + 4*136;
                ah[mf][0] = __float_as_uint(sAh[p0]);
                ah[mf][1] = __float_as_uint(sAh[p0 + 8]);
                ah[mf][2] = __float_as_uint(sAh[p4]);
                ah[mf][3] = __float_as_uint(sAh[p4 + 8]);
                al_[mf][0] = __float_as_uint(sAl[p0]);
                al_[mf][1] = __float_as_uint(sAl[p0 + 8]);
                al_[mf][2] = __float_as_uint(sAl[p4]);
                al_[mf][3] = __float_as_uint(sAl[p4 + 8]);
            }
            #pragma unroll
            for (int nf = 0; nf < 4; nf++) {
                int n = wn*32 + nf*8 + lq;
                int p0 = krow + n, p4 = p0 + 4*136;
                bh[nf][0] = __float_as_uint(sBh[p0]);
                bh[nf][1] = __float_as_uint(sBh[p4]);
                bl_[nf][0] = __float_as_uint(sBl[p0]);
                bl_[nf][1] = __float_as_uint(sBl[p4]);
            }
            #pragma unroll
            for (int mf = 0; mf < 4; mf++)
                #pragma unroll
                for (int nf = 0; nf < 4; nf++) {
                    float* c = acc[mf][nf];
                    mma_tf32(c, ah[mf][0],ah[mf][1],ah[mf][2],ah[mf][3],
                                bh[nf][0],bh[nf][1]);
                    mma_tf32(c, ah[mf][0],ah[mf][1],ah[mf][2],ah[mf][3],
                                bl_[nf][0],bl_[nf][1]);
                    mma_tf32(c, al_[mf][0],al_[mf][1],al_[mf][2],al_[mf][3],
                                bh[nf][0],bh[nf][1]);
                }
        }

        if (kt + 1 < KT) {
            sts(buf ^ 1);
            __syncthreads();
        }
    }

    #pragma unroll
    for (int mf = 0; mf < 4; mf++) {
        int rbase = row0 + wm*64 + mf*16 + lq;
        #pragma unroll
        for (int half = 0; half < 2; half++) {
            int row = rbase + half*8;
            if (row < M) {
                long rres = 0;
                if (EPI == 1) rres = (long)(GATHER ? rowmap[row] : row) * N;
                #pragma unroll
                for (int nf = 0; nf < 4; nf++) {
                    int col = col0 + wn*32 + nf*8 + lr*2;
                    float v0 = acc[mf][nf][half*2+0];
                    float v1 = acc[mf][nf][half*2+1];
                    if (EPI != 0) { v0 += bias[col]; v1 += bias[col+1]; }
                    if (EPI == 2) { v0 = gelu_exact(v0); v1 = gelu_exact(v1); }
                    if (EPI == 1) { v0 += resid[rres+col]; v1 += resid[rres+col+1]; }
                    *(float2*)&Cm[(size_t)row * N + col] = make_float2(v0, v1);
                }
            }
        }
    }
}

// ---------------- Attention (fp32, feeds top-k; unchanged from R5) ----------
__global__ __launch_bounds__(256) void attn_kernel(
    const float* __restrict__ QKV, const float* __restrict__ amask,
    float* __restrict__ XATT, float* __restrict__ CLSH)
{
    extern __shared__ float smx[];
    float* sS  = smx;                 // 32*1024
    float* sQt = smx + 32*1024;       // [64][36]
    float* sT  = sQt + 64*36;         // 8448 floats
    int t = threadIdx.x;
    int n0 = blockIdx.x * 32, h = blockIdx.y, b = blockIdx.z;
    size_t base_bh = (size_t)b * N_ * 2304 + (size_t)h * 64;

    for (int e = t; e < 32*64; e += 256) {
        int i = e >> 6, d = e & 63;
        sQt[d*36 + i] = QKV[base_bh + (size_t)(n0 + i) * 2304 + d];
    }

    int ty = t >> 5, tx = t & 31;

    for (int kt = 0; kt < 8; kt++) {
        int m0 = kt << 7;
        __syncthreads();
        for (int e = t; e < 128*64; e += 256) {
            int m = e >> 6, d = e & 63;
            sT[d*132 + m] = QKV[base_bh + 768 + (size_t)(m0 + m) * 2304 + d];
        }
        __syncthreads();
        float acc[4][4] = {{0.f}};
        #pragma unroll 4
        for (int d = 0; d < 64; d++) {
            float4 aq = *(const float4*)&sQt[d*36 + ty*4];
            float4 bk = *(const float4*)&sT[d*132 + tx*4];
            float ar[4] = {aq.x,aq.y,aq.z,aq.w};
            float br[4] = {bk.x,bk.y,bk.z,bk.w};
            #pragma unroll
            for (int i = 0; i < 4; i++)
                #pragma unroll
                for (int j = 0; j < 4; j++)
                    acc[i][j] = fmaf(ar[i], br[j], acc[i][j]);
        }
        #pragma unroll
        for (int i = 0; i < 4; i++) {
            float4 v = make_float4(acc[i][0]*0.125f, acc[i][1]*0.125f,
                                   acc[i][2]*0.125f, acc[i][3]*0.125f);
            *(float4*)&sS[(ty*4+i)*1024 + m0 + tx*4] = v;
        }
    }
    __syncthreads();

    int lane = t & 31, w = t >> 5;
    for (int rr = 0; rr < 4; rr++) {
        int i = w + rr*8;
        int n = n0 + i;
        float* row = sS + i*1024;
        float mx = -3.4e38f;
        for (int m = lane; m < 1024; m += 32) mx = fmaxf(mx, row[m]);
        #pragma unroll
        for (int o = 16; o; o >>= 1) mx = fmaxf(mx, __shfl_xor_sync(~0u, mx, o));
        const float* mrow = amask + (size_t)(b * N_ + n) * N_;
        float sum = 0.f;
        for (int m = lane; m < 1024; m += 32) {
            float e = expf(row[m] - mx) * mrow[m];
            row[m] = e;
            sum += e;
        }
        #pragma unroll
        for (int o = 16; o; o >>= 1) sum += __shfl_xor_sync(~0u, sum, o);
        float rinv = 1.0f / (sum + 1e-6f);
        const float epsn = 1e-6f / 1024.0f;
        for (int m = lane; m < 1024; m += 32) row[m] = (row[m] + epsn) * rinv;
        if (n == 0) {
            float* cl = CLSH + (size_t)(b * H_ + h) * (N_ - 1);
            for (int m = 1 + lane; m < 1024; m += 32) cl[m-1] = row[m];
        }
    }
    __syncthreads();

    float oacc[4][2] = {{0.f}};
    for (int vt = 0; vt < 8; vt++) {
        int m0 = vt << 7;
        __syncthreads();
        for (int e = t; e < 128*64; e += 256) {
            int m = e >> 6, d = e & 63;
            sT[m*66 + d] = QKV[base_bh + 1536 + (size_t)(m0 + m) * 2304 + d];
        }
        __syncthreads();
        #pragma unroll 4
        for (int m = 0; m < 128; m++) {
            float2 vv = *(const float2*)&sT[m*66 + tx*2];
            #pragma unroll
            for (int i = 0; i < 4; i++) {
                float a = sS[(ty*4+i)*1024 + m0 + m];
                oacc[i][0] = fmaf(a, vv.x, oacc[i][0]);
                oacc[i][1] = fmaf(a, vv.y, oacc[i][1]);
            }
        }
    }
    #pragma unroll
    for (int i = 0; i < 4; i++) {
        int n = n0 + ty*4 + i;
        float2 o2 = make_float2(oacc[i][0], oacc[i][1]);
        *(float2*)&XATT[(size_t)(b * N_ + n) * C_ + h*64 + tx*2] = o2;
    }
}

// ---------------- top-k via bitonic sort (jax.lax.top_k semantics) ----------
__global__ __launch_bounds__(256) void topk_kernel(
    const float* __restrict__ CLSH, int* __restrict__ ROWSEL,
    float* __restrict__ outIA, float* __restrict__ outIM)
{
    __shared__ float sv[1024];
    __shared__ int   si[1024];
    int seg = blockIdx.x, b = blockIdx.y, t = threadIdx.x;
    int P     = seg ? 1024 : 256;
    int count = seg ? 768  : 255;
    int base  = seg ? 255  : 0;

    for (int e = t; e < P; e += 256) {
        if (e < count) {
            float s = 0.f;
            #pragma unroll
            for (int hh = 0; hh < 12; hh++)
                s += CLSH[(size_t)(b*12 + hh) * 1023 + base + e];
            sv[e] = s;
            si[e] = e;
        } else { sv[e] = -3.4e38f; si[e] = 0x7FFFFFFF; }
    }

    for (int k = 2; k <= P; k <<= 1)
        for (int j = k >> 1; j > 0; j >>= 1) {
            __syncthreads();
            for (int i = t; i < P; i += 256) {
                int ixj = i ^ j;
                if (ixj > i) {
                    float v1 = sv[i], v2 = sv[ixj];
                    int a1 = si[i], a2 = si[ixj];
                    bool before12 = (v1 > v2) || (v1 == v2 && a1 < a2);
                    bool up = ((i & k) == 0);
                    if (up != before12) {
                        sv[i] = v2; sv[ixj] = v1; si[i] = a2; si[ixj] = a1;
                    }
                }
            }
        }
    __syncthreads();

    if (seg == 0) {
        if (t < 128) {
            int idx = si[t];
            if (outIA) outIA[b*128 + t] = (float)idx;
            ROWSEL[b*513 + 1 + t] = b*1024 + 1 + idx;
        }
        if (t == 0) ROWSEL[b*513] = b*1024;
    } else {
        for (int e = t; e < 384; e += 256) {
            int idx = si[e];
            if (outIM) outIM[b*384 + e] = (float)idx;
            ROWSEL[b*513 + 129 + e] = b*1024 + 256 + idx;
        }
    }
}

__global__ void fill_ones(float* __restrict__ p, int n) {
    int i = blockIdx.x * 256 + threadIdx.x;
    if (i < n) p[i] = 1.0f;
}

// ---------------- launcher ----------------
extern "C" void kernel_launch(void* const* d_in, const int* in_sizes, int n_in,
                              void* d_out, int out_size)
{
    const float* x      = (const float*)d_in[0];
    const float* amask  = (const float*)d_in[1];
    const float* w_qkv  = (const float*)d_in[4];
    const float* w_proj = (const float*)d_in[5];
    const float* b_proj = (const float*)d_in[6];
    const float* g1     = (const float*)d_in[7];
    const float* b1     = (const float*)d_in[8];
    const float* g2     = (const float*)d_in[9];
    const float* b2     = (const float*)d_in[10];
    const float* w_fc1  = (const float*)d_in[11];
    const float* b_fc1  = (const float*)d_in[12];
    const float* w_fc2  = (const float*)d_in[13];
    const float* b_fc2  = (const float*)d_in[14];
    float* out = (float*)d_out;

    float *XN, *QKV, *XATT, *CLSH, *XP, *XN2, *HB; int* ROWSEL;
    cudaGetSymbolAddress((void**)&XN,   g_XN);
    cudaGetSymbolAddress((void**)&QKV,  g_QKV);
    cudaGetSymbolAddress((void**)&XATT, g_XATT);
    cudaGetSymbolAddress((void**)&CLSH, g_CLSH);
    cudaGetSymbolAddress((void**)&XP,   g_XP);
    cudaGetSymbolAddress((void**)&XN2,  g_XN2);
    cudaGetSymbolAddress((void**)&HB,   g_HB);
    cudaGetSymbolAddress((void**)&ROWSEL, g_ROWSEL);

    const int ATTN_SMEM = (32*1024 + 64*36 + 8448) * 4;  // 174080 B
    cudaFuncSetAttribute(attn_kernel,
        cudaFuncAttributeMaxDynamicSharedMemorySize, ATTN_SMEM);

    const int GEMM_SMEM = 17408 * 4;  // 69632 B
    cudaFuncSetAttribute(mma_gemm<true,1>,
        cudaFuncAttributeMaxDynamicSharedMemorySize, GEMM_SMEM);
    cudaFuncSetAttribute(mma_gemm<false,1>,
        cudaFuncAttributeMaxDynamicSharedMemorySize, GEMM_SMEM);
    cudaFuncSetAttribute(mma_gemm<false,2>,
        cudaFuncAttributeMaxDynamicSharedMemorySize, GEMM_SMEM);

    const int OFF_IA = 8*513*768;
    const int OFF_IM = OFF_IA + 8*128;
    const int OFF_MK = OFF_IM + 8*384;
    const int MK_SZ  = 8*513*513;
    const int TOTAL  = OFF_MK + MK_SZ;
    float* outIA = (out_size >= TOTAL) ? out + OFF_IA : nullptr;
    float* outIM = (out_size >= TOTAL) ? out + OFF_IM : nullptr;

    // 1. LN1
    ln_kernel<<<B_*N_, 256>>>(x, g1, b1, XN);
    // 2. QKV GEMM [8192,768]@[768,2304] — fp32 exact (feeds top-k via Q,K)
    sgemm_kernel<<<dim3(2304/128, 8192/128), 256>>>(
        XN, w_qkv, QKV, B_*N_, 3*C_, C_);
    // 3. attention (fp32, writes XATT + per-head cls rows)
    attn_kernel<<<dim3(N_/32, H_, B_), 256, ATTN_SMEM>>>(QKV, amask, XATT, CLSH);
    // 4. top-k
    topk_kernel<<<dim3(2, B_), 256>>>(CLSH, ROWSEL, outIA, outIM);
    // 5. gathered proj (3xTF32): XP = x[sel] + (XATT[sel] @ w_proj + b_proj)
    mma_gemm<true,1><<<dim3(768/128, (MROWS+127)/128), 256, GEMM_SMEM>>>(
        XATT, w_proj, XP, MROWS, C_, C_, b_proj, x, ROWSEL);
    // 6. LN2
    ln_kernel<<<MROWS, 256>>>(XP, g2, b2, XN2);
    // 7. fc1 + GELU (3xTF32)
    mma_gemm<false,2><<<dim3(3072/128, (MROWS+127)/128), 256, GEMM_SMEM>>>(
        XN2, w_fc1, HB, MROWS, HID_, C_, b_fc1, nullptr, nullptr);
    // 8. fc2 + bias + residual -> d_out (3xTF32)
    mma_gemm<false,1><<<dim3(768/128, (MROWS+127)/128), 256, GEMM_SMEM>>>(
        HB, w_fc2, out, MROWS, C_, HID_, b_fc2, XP, nullptr);
    // 9. new_mask == all ones (proved in R4)
    if (out_size >= TOTAL)
        fill_ones<<<(MK_SZ + 255)/256, 256>>>(out + OFF_MK, MK_SZ);
}

// round 10
// speedup vs baseline: 1.4479x; 1.4157x over previous
#include <cuda_runtime.h>
#include <cuda_bf16.h>
#include <cstdint>
#include <math.h>

#define B_   8
#define N_   1024
#define C_   768
#define H_   12
#define HID_ 3072
#define RN_  513
#define MROWS (B_*RN_)   // 4104

// ---------------- scratch (static __device__, no allocation) ----------------
__device__ float g_XN  [B_*N_*C_];
__device__ float g_QKV [B_*N_*3*C_];   // only K,V region (cols 768..2303) used
__device__ float g_QG  [MROWS*C_];     // gathered Q (compact)
__device__ float g_XATT[MROWS*C_];     // attention out (compact, selected rows)
__device__ float g_CLSH[B_*H_*(N_-1)];
__device__ int   g_ROWSEL[B_*RN_];
__device__ float g_XP  [MROWS*C_];
__device__ float g_XN2 [MROWS*C_];
__device__ float g_HB  [MROWS*HID_];

__device__ __forceinline__ float gelu_exact(float v) {
    return 0.5f * v * (1.0f + erff(v * 0.70710678118654752f));
}

// split fp32 into two truncated-tf32 parts: v ~= hi + lo
__device__ __forceinline__ void splitf(float v, float& hi, float& lo) {
    unsigned uh = __float_as_uint(v) & 0xffffe000u;
    hi = __uint_as_float(uh);
    float l = v - hi;
    lo = __uint_as_float(__float_as_uint(l) & 0xffffe000u);
}

__device__ __forceinline__ void mma_tf32(float* c,
    unsigned a0, unsigned a1, unsigned a2, unsigned a3,
    unsigned b0, unsigned b1)
{
    asm volatile(
        "mma.sync.aligned.m16n8k8.row.col.f32.tf32.tf32.f32 "
        "{%0,%1,%2,%3},{%4,%5,%6,%7},{%8,%9},{%0,%1,%2,%3};"
        : "+f"(c[0]), "+f"(c[1]), "+f"(c[2]), "+f"(c[3])
        : "r"(a0), "r"(a1), "r"(a2), "r"(a3), "r"(b0), "r"(b1));
}

// ---------------- LayerNorm (1 row / block, C=768, 256 threads) -------------
__global__ __launch_bounds__(256) void ln_kernel(
    const float* __restrict__ X, const float* __restrict__ g,
    const float* __restrict__ bt, float* __restrict__ Y)
{
    __shared__ float red[8];
    int row = blockIdx.x, t = threadIdx.x;
    const float* xr = X + (size_t)row * C_;
    float x0 = xr[t], x1 = xr[t+256], x2 = xr[t+512];
    float s = x0 + x1 + x2;
    #pragma unroll
    for (int o = 16; o; o >>= 1) s += __shfl_xor_sync(~0u, s, o);
    if ((t & 31) == 0) red[t >> 5] = s;
    __syncthreads();
    float tot = 0.f;
    #pragma unroll
    for (int i = 0; i < 8; i++) tot += red[i];
    float mean = tot * (1.0f/768.0f);
    __syncthreads();
    float d0 = x0-mean, d1 = x1-mean, d2 = x2-mean;
    float q = d0*d0 + d1*d1 + d2*d2;
    #pragma unroll
    for (int o = 16; o; o >>= 1) q += __shfl_xor_sync(~0u, q, o);
    if ((t & 31) == 0) red[t >> 5] = q;
    __syncthreads();
    float tq = 0.f;
    #pragma unroll
    for (int i = 0; i < 8; i++) tq += red[i];
    float rstd = 1.0f / sqrtf(tq * (1.0f/768.0f) + 1e-5f);
    float* yr = Y + (size_t)row * C_;
    yr[t]     = d0*rstd*g[t]     + bt[t];
    yr[t+256] = d1*rstd*g[t+256] + bt[t+256];
    yr[t+512] = d2*rstd*g[t+512] + bt[t+512];
}

// ------- fp32 SGEMM w/ strides + optional row gather: 128x128x8, 8x8 -------
template<bool GATHER>
__global__ __launch_bounds__(256) void sgemm2(
    const float* __restrict__ A, int lda,
    const float* __restrict__ Bm, int ldb,
    float* __restrict__ Cm, int ldc,
    int M, int N, int K, const int* __restrict__ rowmap)
{
    __shared__ float As[8][128];
    __shared__ float Bs[8][128];
    int t = threadIdx.x;
    int row0 = blockIdx.y * 128, col0 = blockIdx.x * 128;

    int la_r = t >> 1, la_k = (t & 1) * 4;
    long a_base = -1;
    {
        int arow = row0 + la_r;
        if (arow < M) a_base = (long)(GATHER ? rowmap[arow] : arow) * lda;
    }
    int lb_k = t >> 5, lb_c = (t & 31) * 4;
    const float* bp = Bm + (size_t)lb_k * ldb + col0 + lb_c;

    int ty = t >> 4, tx = t & 15;
    float acc[8][8] = {{0.f}};

    float4 av = make_float4(0.f,0.f,0.f,0.f), bv;
    if (a_base >= 0) av = *(const float4*)(A + a_base + la_k);
    bv = *(const float4*)bp;

    for (int k0 = 0; k0 < K; k0 += 8) {
        __syncthreads();
        As[la_k  ][la_r] = av.x;  As[la_k+1][la_r] = av.y;
        As[la_k+2][la_r] = av.z;  As[la_k+3][la_r] = av.w;
        *(float4*)&Bs[lb_k][lb_c] = bv;
        __syncthreads();
        if (k0 + 8 < K) {
            if (a_base >= 0) av = *(const float4*)(A + a_base + k0 + 8 + la_k);
            bv = *(const float4*)(bp + (size_t)(k0 + 8) * ldb);
        }
        #pragma unroll
        for (int kk = 0; kk < 8; kk++) {
            float4 a0 = *(const float4*)&As[kk][ty*8];
            float4 a1 = *(const float4*)&As[kk][ty*8+4];
            float4 b0 = *(const float4*)&Bs[kk][tx*8];
            float4 b1 = *(const float4*)&Bs[kk][tx*8+4];
            float ar[8] = {a0.x,a0.y,a0.z,a0.w,a1.x,a1.y,a1.z,a1.w};
            float br[8] = {b0.x,b0.y,b0.z,b0.w,b1.x,b1.y,b1.z,b1.w};
            #pragma unroll
            for (int i = 0; i < 8; i++)
                #pragma unroll
                for (int j = 0; j < 8; j++)
                    acc[i][j] = fmaf(ar[i], br[j], acc[i][j]);
        }
    }

    #pragma unroll
    for (int i = 0; i < 8; i++) {
        int row = row0 + ty*8 + i;
        if (row < M) {
            #pragma unroll
            for (int jj = 0; jj < 8; jj += 4) {
                int col = col0 + tx*8 + jj;
                float4 v = make_float4(acc[i][jj], acc[i][jj+1], acc[i][jj+2], acc[i][jj+3]);
                *(float4*)&Cm[(size_t)row * ldc + col] = v;
            }
        }
    }
}

// ---------------- 3xTF32 MMA GEMM (validated in R7): 128x128, BK=16 ---------
// GA: gather A rows; GR: gather residual rows. EPI: 0 plain, 1 +bias+resid, 2 +bias+GELU
template<bool GA, bool GR, int EPI>
__global__ __launch_bounds__(256) void mma_gemm(
    const float* __restrict__ A, const float* __restrict__ Bm, float* __restrict__ Cm,
    int M, int N, int K,
    const float* __restrict__ bias, const float* __restrict__ resid,
    const int* __restrict__ rowmap)
{
    extern __shared__ float sm[];
    float* sAh = sm;
    float* sAl = sm + 4352;
    float* sBh = sm + 8704;
    float* sBl = sm + 13056;

    const int t    = threadIdx.x;
    const int lane = t & 31, wid = t >> 5;
    const int lq = lane >> 2, lr = lane & 3;
    const int wm = wid & 1,  wn = wid >> 1;
    const int row0 = blockIdx.y * 128, col0 = blockIdx.x * 128;

    const int am = t & 127, ak0 = (t >> 7) * 8;
    long a_base = -1;
    {
        int arow = row0 + am;
        if (arow < M) a_base = (long)(GA ? rowmap[arow] : arow) * K;
    }
    const int bk = wid, bn = lane * 4;
    const float* bptr = Bm + (size_t)bk * N + col0 + bn;

    float acc[4][4][4];
    #pragma unroll
    for (int i = 0; i < 4; i++)
        #pragma unroll
        for (int j = 0; j < 4; j++)
            #pragma unroll
            for (int q = 0; q < 4; q++) acc[i][j][q] = 0.f;

    float4 aR0, aR1, bR0, bR1;

    auto ldg = [&](int kt) {
        if (a_base >= 0) {
            aR0 = *(const float4*)(A + a_base + kt*16 + ak0);
            aR1 = *(const float4*)(A + a_base + kt*16 + ak0 + 4);
        } else {
            aR0 = make_float4(0.f,0.f,0.f,0.f);
            aR1 = make_float4(0.f,0.f,0.f,0.f);
        }
        bR0 = *(const float4*)(bptr + (size_t)(kt*16) * N);
        bR1 = *(const float4*)(bptr + (size_t)(kt*16 + 8) * N);
    };
    auto sts = [&](int buf) {
        float va[8] = {aR0.x,aR0.y,aR0.z,aR0.w,aR1.x,aR1.y,aR1.z,aR1.w};
        int ab = buf*2176 + ak0*136 + am;
        #pragma unroll
        for (int j = 0; j < 8; j++) {
            float h, l; splitf(va[j], h, l);
            sAh[ab + j*136] = h;
            sAl[ab + j*136] = l;
        }
        float vb[8] = {bR0.x,bR0.y,bR0.z,bR0.w,bR1.x,bR1.y,bR1.z,bR1.w};
        float hb[8], lb[8];
        #pragma unroll
        for (int j = 0; j < 8; j++) splitf(vb[j], hb[j], lb[j]);
        int b0 = buf*2176 + bk*136 + bn;
        int b1 = b0 + 8*136;
        *(float4*)&sBh[b0] = make_float4(hb[0],hb[1],hb[2],hb[3]);
        *(float4*)&sBl[b0] = make_float4(lb[0],lb[1],lb[2],lb[3]);
        *(float4*)&sBh[b1] = make_float4(hb[4],hb[5],hb[6],hb[7]);
        *(float4*)&sBl[b1] = make_float4(lb[4],lb[5],lb[6],lb[7]);
    };

    const int KT = K >> 4;
    ldg(0);
    sts(0);
    __syncthreads();

    for (int kt = 0; kt < KT; ++kt) {
        const int buf = kt & 1;
        if (kt + 1 < KT) ldg(kt + 1);

        #pragma unroll
        for (int ks = 0; ks < 2; ks++) {
            const int krow = buf*2176 + (ks*8 + lr)*136;
            unsigned ah[4][4], al_[4][4], bh[4][2], bl_[4][2];
            #pragma unroll
            for (int mf = 0; mf < 4; mf++) {
                int m = wm*64 + mf*16 + lq;
                int p0 = krow + m, p4 = p0 + 4*136;
                ah[mf][0] = __float_as_uint(sAh[p0]);
                ah[mf][1] = __float_as_uint(sAh[p0 + 8]);
                ah[mf][2] = __float_as_uint(sAh[p4]);
                ah[mf][3] = __float_as_uint(sAh[p4 + 8]);
                al_[mf][0] = __float_as_uint(sAl[p0]);
                al_[mf][1] = __float_as_uint(sAl[p0 + 8]);
                al_[mf][2] = __float_as_uint(sAl[p4]);
                al_[mf][3] = __float_as_uint(sAl[p4 + 8]);
            }
            #pragma unroll
            for (int nf = 0; nf < 4; nf++) {
                int n = wn*32 + nf*8 + lq;
                int p0 = krow + n, p4 = p0 + 4*136;
                bh[nf][0] = __float_as_uint(sBh[p0]);
                bh[nf][1] = __float_as_uint(sBh[p4]);
                bl_[nf][0] = __float_as_uint(sBl[p0]);
                bl_[nf][1] = __float_as_uint(sBl[p4]);
            }
            #pragma unroll
            for (int mf = 0; mf < 4; mf++)
                #pragma unroll
                for (int nf = 0; nf < 4; nf++) {
                    float* c = acc[mf][nf];
                    mma_tf32(c, ah[mf][0],ah[mf][1],ah[mf][2],ah[mf][3],
                                bh[nf][0],bh[nf][1]);
                    mma_tf32(c, ah[mf][0],ah[mf][1],ah[mf][2],ah[mf][3],
                                bl_[nf][0],bl_[nf][1]);
                    mma_tf32(c, al_[mf][0],al_[mf][1],al_[mf][2],al_[mf][3],
                                bh[nf][0],bh[nf][1]);
                }
        }

        if (kt + 1 < KT) {
            sts(buf ^ 1);
            __syncthreads();
        }
    }

    #pragma unroll
    for (int mf = 0; mf < 4; mf++) {
        int rbase = row0 + wm*64 + mf*16 + lq;
        #pragma unroll
        for (int half = 0; half < 2; half++) {
            int row = rbase + half*8;
            if (row < M) {
                long rres = 0;
                if (EPI == 1) rres = (long)(GR ? rowmap[row] : row) * N;
                #pragma unroll
                for (int nf = 0; nf < 4; nf++) {
                    int col = col0 + wn*32 + nf*8 + lr*2;
                    float v0 = acc[mf][nf][half*2+0];
                    float v1 = acc[mf][nf][half*2+1];
                    if (EPI != 0) { v0 += bias[col]; v1 += bias[col+1]; }
                    if (EPI == 2) { v0 = gelu_exact(v0); v1 = gelu_exact(v1); }
                    if (EPI == 1) { v0 += resid[rres+col]; v1 += resid[rres+col+1]; }
                    *(float2*)&Cm[(size_t)row * N + col] = make_float2(v0, v1);
                }
            }
        }
    }
}

// ------------- cls attention row (q0 = xn0 @ Wq, softmax, -> CLSH) ----------
__global__ __launch_bounds__(256) void cls_kernel(
    const float* __restrict__ XN, const float* __restrict__ wqkv,
    const float* __restrict__ QKV, const float* __restrict__ amask,
    float* __restrict__ CLSH)
{
    __shared__ float q0[64];
    __shared__ float sS[1024];
    __shared__ float red[8];
    int h = blockIdx.x, b = blockIdx.y, t = threadIdx.x;

    // q0[d] over 4 lane-adjacent partial sums of 192
    {
        int d = t >> 2, part = t & 3;
        const float* xr = XN + (size_t)b * N_ * C_;
        const float* wc = wqkv + h*64 + d;
        float s = 0.f;
        int k0 = part * 192;
        for (int k = k0; k < k0 + 192; k++)
            s = fmaf(xr[k], wc[(size_t)k * 2304], s);
        s += __shfl_xor_sync(~0u, s, 1);
        s += __shfl_xor_sync(~0u, s, 2);
        if (part == 0) q0[d] = s;
    }
    __syncthreads();

    // scores vs all K
    float sv[4];
    #pragma unroll
    for (int j = 0; j < 4; j++) {
        int m = t + 256*j;
        const float* kr = QKV + (size_t)(b*N_ + m)*2304 + 768 + h*64;
        float acc = 0.f;
        #pragma unroll
        for (int d = 0; d < 64; d++) acc = fmaf(q0[d], kr[d], acc);
        sv[j] = acc * 0.125f;
    }
    float mx = fmaxf(fmaxf(sv[0], sv[1]), fmaxf(sv[2], sv[3]));
    #pragma unroll
    for (int o = 16; o; o >>= 1) mx = fmaxf(mx, __shfl_xor_sync(~0u, mx, o));
    if ((t & 31) == 0) red[t >> 5] = mx;
    __syncthreads();
    mx = red[0];
    #pragma unroll
    for (int i = 1; i < 8; i++) mx = fmaxf(mx, red[i]);

    const float* mrow = amask + (size_t)b * N_ * N_;  // mask row n=0
    float sum = 0.f;
    #pragma unroll
    for (int j = 0; j < 4; j++) {
        int m = t + 256*j;
        float e = expf(sv[j] - mx) * mrow[m];
        sS[m] = e;
        sum += e;
    }
    #pragma unroll
    for (int o = 16; o; o >>= 1) sum += __shfl_xor_sync(~0u, sum, o);
    __syncthreads();
    if ((t & 31) == 0) red[t >> 5] = sum;
    __syncthreads();
    sum = 0.f;
    #pragma unroll
    for (int i = 0; i < 8; i++) sum += red[i];
    float rinv = 1.0f / (sum + 1e-6f);
    const float epsn = 1e-6f / 1024.0f;
    float* cl = CLSH + (size_t)(b*H_ + h) * (N_ - 1);
    #pragma unroll
    for (int j = 0; j < 4; j++) {
        int m = t + 256*j;
        if (m >= 1) cl[m-1] = (sS[m] + epsn) * rinv;
    }
}

// --------- Attention for SELECTED rows: block = (32 compact rows, h, b) -----
__global__ __launch_bounds__(256) void attn_sel_kernel(
    const float* __restrict__ QG, const float* __restrict__ QKV,
    const float* __restrict__ amask, const int* __restrict__ ROWSEL,
    float* __restrict__ XATT)
{
    extern __shared__ float smx[];
    float* sS  = smx;                 // 32*1024
    float* sQt = smx + 32*1024;       // [64][36]
    float* sT  = sQt + 64*36;         // 8448 floats
    int t = threadIdx.x;
    int n0 = blockIdx.x * 32, h = blockIdx.y, b = blockIdx.z;
    size_t base_bh = (size_t)b * N_ * 2304 + (size_t)h * 64;

    // Q tile from compact gathered-Q
    for (int e = t; e < 32*64; e += 256) {
        int i = e >> 6, d = e & 63;
        int r = n0 + i;
        sQt[d*36 + i] = (r < RN_)
            ? QG[(size_t)(b*RN_ + r) * C_ + h*64 + d] : 0.f;
    }

    int ty = t >> 5, tx = t & 31;

    // scores S = (Q K^T) * 0.125
    for (int kt = 0; kt < 8; kt++) {
        int m0 = kt << 7;
        __syncthreads();
        for (int e = t; e < 128*64; e += 256) {
            int m = e >> 6, d = e & 63;
            sT[d*132 + m] = QKV[base_bh + 768 + (size_t)(m0 + m) * 2304 + d];
        }
        __syncthreads();
        float acc[4][4] = {{0.f}};
        #pragma unroll 4
        for (int d = 0; d < 64; d++) {
            float4 aq = *(const float4*)&sQt[d*36 + ty*4];
            float4 bk = *(const float4*)&sT[d*132 + tx*4];
            float ar[4] = {aq.x,aq.y,aq.z,aq.w};
            float br[4] = {bk.x,bk.y,bk.z,bk.w};
            #pragma unroll
            for (int i = 0; i < 4; i++)
                #pragma unroll
                for (int j = 0; j < 4; j++)
                    acc[i][j] = fmaf(ar[i], br[j], acc[i][j]);
        }
        #pragma unroll
        for (int i = 0; i < 4; i++) {
            float4 v = make_float4(acc[i][0]*0.125f, acc[i][1]*0.125f,
                                   acc[i][2]*0.125f, acc[i][3]*0.125f);
            *(float4*)&sS[(ty*4+i)*1024 + m0 + tx*4] = v;
        }
    }
    __syncthreads();

    // softmax per valid row
    int lane = t & 31, w = t >> 5;
    for (int rr = 0; rr < 4; rr++) {
        int i = w + rr*8;
        int r = n0 + i;
        if (r >= RN_) continue;
        int norig = ROWSEL[b*RN_ + r] - b*1024;
        float* row = sS + i*1024;
        float mx = -3.4e38f;
        for (int m = lane; m < 1024; m += 32) mx = fmaxf(mx, row[m]);
        #pragma unroll
        for (int o = 16; o; o >>= 1) mx = fmaxf(mx, __shfl_xor_sync(~0u, mx, o));
        const float* mrow = amask + (size_t)(b * N_ + norig) * N_;
        float sum = 0.f;
        for (int m = lane; m < 1024; m += 32) {
            float e = expf(row[m] - mx) * mrow[m];
            row[m] = e;
            sum += e;
        }
        #pragma unroll
        for (int o = 16; o; o >>= 1) sum += __shfl_xor_sync(~0u, sum, o);
        float rinv = 1.0f / (sum + 1e-6f);
        const float epsn = 1e-6f / 1024.0f;
        for (int m = lane; m < 1024; m += 32) row[m] = (row[m] + epsn) * rinv;
    }
    __syncthreads();

    // AV
    float oacc[4][2] = {{0.f}};
    for (int vt = 0; vt < 8; vt++) {
        int m0 = vt << 7;
        __syncthreads();
        for (int e = t; e < 128*64; e += 256) {
            int m = e >> 6, d = e & 63;
            sT[m*66 + d] = QKV[base_bh + 1536 + (size_t)(m0 + m) * 2304 + d];
        }
        __syncthreads();
        #pragma unroll 4
        for (int m = 0; m < 128; m++) {
            float2 vv = *(const float2*)&sT[m*66 + tx*2];
            #pragma unroll
            for (int i = 0; i < 4; i++) {
                float a = sS[(ty*4+i)*1024 + m0 + m];
                oacc[i][0] = fmaf(a, vv.x, oacc[i][0]);
                oacc[i][1] = fmaf(a, vv.y, oacc[i][1]);
            }
        }
    }
    #pragma unroll
    for (int i = 0; i < 4; i++) {
        int r = n0 + ty*4 + i;
        if (r < RN_) {
            float2 o2 = make_float2(oacc[i][0], oacc[i][1]);
            *(float2*)&XATT[(size_t)(b*RN_ + r) * C_ + h*64 + tx*2] = o2;
        }
    }
}

// ---------------- top-k via bitonic sort (jax.lax.top_k semantics) ----------
__global__ __launch_bounds__(256) void topk_kernel(
    const float* __restrict__ CLSH, int* __restrict__ ROWSEL,
    float* __restrict__ outIA, float* __restrict__ outIM)
{
    __shared__ float sv[1024];
    __shared__ int   si[1024];
    int seg = blockIdx.x, b = blockIdx.y, t = threadIdx.x;
    int P     = seg ? 1024 : 256;
    int count = seg ? 768  : 255;
    int base  = seg ? 255  : 0;

    for (int e = t; e < P; e += 256) {
        if (e < count) {
            float s = 0.f;
            #pragma unroll
            for (int hh = 0; hh < 12; hh++)
                s += CLSH[(size_t)(b*12 + hh) * 1023 + base + e];
            sv[e] = s;
            si[e] = e;
        } else { sv[e] = -3.4e38f; si[e] = 0x7FFFFFFF; }
    }

    for (int k = 2; k <= P; k <<= 1)
        for (int j = k >> 1; j > 0; j >>= 1) {
            __syncthreads();
            for (int i = t; i < P; i += 256) {
                int ixj = i ^ j;
                if (ixj > i) {
                    float v1 = sv[i], v2 = sv[ixj];
                    int a1 = si[i], a2 = si[ixj];
                    bool before12 = (v1 > v2) || (v1 == v2 && a1 < a2);
                    bool up = ((i & k) == 0);
                    if (up != before12) {
                        sv[i] = v2; sv[ixj] = v1; si[i] = a2; si[ixj] = a1;
                    }
                }
            }
        }
    __syncthreads();

    if (seg == 0) {
        if (t < 128) {
            int idx = si[t];
            if (outIA) outIA[b*128 + t] = (float)idx;
            ROWSEL[b*513 + 1 + t] = b*1024 + 1 + idx;
        }
        if (t == 0) ROWSEL[b*513] = b*1024;
    } else {
        for (int e = t; e < 384; e += 256) {
            int idx = si[e];
            if (outIM) outIM[b*384 + e] = (float)idx;
            ROWSEL[b*513 + 129 + e] = b*1024 + 256 + idx;
        }
    }
}

__global__ void fill_ones(float* __restrict__ p, int n) {
    int i = blockIdx.x * 256 + threadIdx.x;
    if (i < n) p[i] = 1.0f;
}

// ---------------- launcher ----------------
extern "C" void kernel_launch(void* const* d_in, const int* in_sizes, int n_in,
                              void* d_out, int out_size)
{
    const float* x      = (const float*)d_in[0];
    const float* amask  = (const float*)d_in[1];
    const float* w_qkv  = (const float*)d_in[4];
    const float* w_proj = (const float*)d_in[5];
    const float* b_proj = (const float*)d_in[6];
    const float* g1     = (const float*)d_in[7];
    const float* b1     = (const float*)d_in[8];
    const float* g2     = (const float*)d_in[9];
    const float* b2     = (const float*)d_in[10];
    const float* w_fc1  = (const float*)d_in[11];
    const float* b_fc1  = (const float*)d_in[12];
    const float* w_fc2  = (const float*)d_in[13];
    const float* b_fc2  = (const float*)d_in[14];
    float* out = (float*)d_out;

    float *XN, *QKV, *QG, *XATT, *CLSH, *XP, *XN2, *HB; int* ROWSEL;
    cudaGetSymbolAddress((void**)&XN,   g_XN);
    cudaGetSymbolAddress((void**)&QKV,  g_QKV);
    cudaGetSymbolAddress((void**)&QG,   g_QG);
    cudaGetSymbolAddress((void**)&XATT, g_XATT);
    cudaGetSymbolAddress((void**)&CLSH, g_CLSH);
    cudaGetSymbolAddress((void**)&XP,   g_XP);
    cudaGetSymbolAddress((void**)&XN2,  g_XN2);
    cudaGetSymbolAddress((void**)&HB,   g_HB);
    cudaGetSymbolAddress((void**)&ROWSEL, g_ROWSEL);

    const int ATTN_SMEM = (32*1024 + 64*36 + 8448) * 4;  // 174080 B
    cudaFuncSetAttribute(attn_sel_kernel,
        cudaFuncAttributeMaxDynamicSharedMemorySize, ATTN_SMEM);

    const int GEMM_SMEM = 17408 * 4;  // 69632 B
    cudaFuncSetAttribute(mma_gemm<false,true,1>,
        cudaFuncAttributeMaxDynamicSharedMemorySize, GEMM_SMEM);
    cudaFuncSetAttribute(mma_gemm<false,false,1>,
        cudaFuncAttributeMaxDynamicSharedMemorySize, GEMM_SMEM);
    cudaFuncSetAttribute(mma_gemm<false,false,2>,
        cudaFuncAttributeMaxDynamicSharedMemorySize, GEMM_SMEM);

    const int OFF_IA = 8*513*768;
    const int OFF_IM = OFF_IA + 8*128;
    const int OFF_MK = OFF_IM + 8*384;
    const int MK_SZ  = 8*513*513;
    const int TOTAL  = OFF_MK + MK_SZ;
    float* outIA = (out_size >= TOTAL) ? out + OFF_IA : nullptr;
    float* outIM = (out_size >= TOTAL) ? out + OFF_IM : nullptr;

    // 1. LN1 (all rows — feeds K,V everywhere and Q for selected rows)
    ln_kernel<<<B_*N_, 256>>>(x, g1, b1, XN);
    // 2. K,V GEMM only: [8192,768] @ w_qkv[:,768:2304] -> QKV cols 768..2303
    sgemm2<false><<<dim3(1536/128, 8192/128), 256>>>(
        XN, C_, w_qkv + 768, 3*C_, QKV + 768, 3*C_, B_*N_, 2*C_, C_, nullptr);
    // 3. cls attention row (fp32) -> CLSH
    cls_kernel<<<dim3(H_, B_), 256>>>(XN, w_qkv, QKV, amask, CLSH);
    // 4. top-k -> ROWSEL + idx outputs
    topk_kernel<<<dim3(2, B_), 256>>>(CLSH, ROWSEL, outIA, outIM);
    // 5. gathered Q GEMM: QG[4104,768] = XN[sel] @ w_qkv[:,0:768]
    sgemm2<true><<<dim3(768/128, (MROWS+127)/128), 256>>>(
        XN, C_, w_qkv, 3*C_, QG, C_, MROWS, C_, C_, ROWSEL);
    // 6. attention for selected rows only
    attn_sel_kernel<<<dim3((RN_+31)/32, H_, B_), 256, ATTN_SMEM>>>(
        QG, QKV, amask, ROWSEL, XATT);
    // 7. proj: XP = x[sel] + (XATT_compact @ w_proj + b_proj)
    mma_gemm<false,true,1><<<dim3(768/128, (MROWS+127)/128), 256, GEMM_SMEM>>>(
        XATT, w_proj, XP, MROWS, C_, C_, b_proj, x, ROWSEL);
    // 8. LN2
    ln_kernel<<<MROWS, 256>>>(XP, g2, b2, XN2);
    // 9. fc1 + GELU
    mma_gemm<false,false,2><<<dim3(3072/128, (MROWS+127)/128), 256, GEMM_SMEM>>>(
        XN2, w_fc1, HB, MROWS, HID_, C_, b_fc1, nullptr, nullptr);
    // 10. fc2 + bias + residual -> d_out
    mma_gemm<false,false,1><<<dim3(768/128, (MROWS+127)/128), 256, GEMM_SMEM>>>(
        HB, w_fc2, out, MROWS, C_, HID_, b_fc2, XP, nullptr);
    // 11. new_mask == all ones (proved in R4)
    if (out_size >= TOTAL)
        fill_ones<<<(MK_SZ + 255)/256, 256>>>(out + OFF_MK, MK_SZ);
}

// round 11
// speedup vs baseline: 1.7923x; 1.2379x over previous
#include <cuda_runtime.h>
#include <cuda_bf16.h>
#include <cstdint>
#include <math.h>

#define B_   8
#define N_   1024
#define C_   768
#define H_   12
#define HID_ 3072
#define RN_  513
#define MROWS (B_*RN_)   // 4104

// ---------------- scratch (static __device__, no allocation) ----------------
__device__ float g_XN  [B_*N_*C_];
__device__ float g_QKV [B_*N_*3*C_];   // K,V region (cols 768..2303) used
__device__ float g_QG  [MROWS*C_];
__device__ float g_XATT[MROWS*C_];
__device__ float g_CLSH[B_*H_*(N_-1)];
__device__ int   g_ROWSEL[B_*RN_];
__device__ float g_XP  [MROWS*C_];
__device__ float g_XN2 [MROWS*C_];
__device__ float g_HB  [MROWS*HID_];

__device__ __forceinline__ float gelu_exact(float v) {
    return 0.5f * v * (1.0f + erff(v * 0.70710678118654752f));
}

// ---------------- LayerNorm (1 row / block, C=768, 256 threads) -------------
__global__ __launch_bounds__(256) void ln_kernel(
    const float* __restrict__ X, const float* __restrict__ g,
    const float* __restrict__ bt, float* __restrict__ Y)
{
    __shared__ float red[8];
    int row = blockIdx.x, t = threadIdx.x;
    const float* xr = X + (size_t)row * C_;
    float x0 = xr[t], x1 = xr[t+256], x2 = xr[t+512];
    float s = x0 + x1 + x2;
    #pragma unroll
    for (int o = 16; o; o >>= 1) s += __shfl_xor_sync(~0u, s, o);
    if ((t & 31) == 0) red[t >> 5] = s;
    __syncthreads();
    float tot = 0.f;
    #pragma unroll
    for (int i = 0; i < 8; i++) tot += red[i];
    float mean = tot * (1.0f/768.0f);
    __syncthreads();
    float d0 = x0-mean, d1 = x1-mean, d2 = x2-mean;
    float q = d0*d0 + d1*d1 + d2*d2;
    #pragma unroll
    for (int o = 16; o; o >>= 1) q += __shfl_xor_sync(~0u, q, o);
    if ((t & 31) == 0) red[t >> 5] = q;
    __syncthreads();
    float tq = 0.f;
    #pragma unroll
    for (int i = 0; i < 8; i++) tq += red[i];
    float rstd = 1.0f / sqrtf(tq * (1.0f/768.0f) + 1e-5f);
    float* yr = Y + (size_t)row * C_;
    yr[t]     = d0*rstd*g[t]     + bt[t];
    yr[t+256] = d1*rstd*g[t+256] + bt[t+256];
    yr[t+512] = d2*rstd*g[t+512] + bt[t+512];
}

// ------- fp32 SGEMM w/ strides (exact path for K): 128x128x8, 8x8 ----------
template<bool GATHER>
__global__ __launch_bounds__(256) void sgemm2(
    const float* __restrict__ A, int lda,
    const float* __restrict__ Bm, int ldb,
    float* __restrict__ Cm, int ldc,
    int M, int N, int K, const int* __restrict__ rowmap)
{
    __shared__ float As[8][128];
    __shared__ float Bs[8][128];
    int t = threadIdx.x;
    int row0 = blockIdx.y * 128, col0 = blockIdx.x * 128;

    int la_r = t >> 1, la_k = (t & 1) * 4;
    long a_base = -1;
    {
        int arow = row0 + la_r;
        if (arow < M) a_base = (long)(GATHER ? rowmap[arow] : arow) * lda;
    }
    int lb_k = t >> 5, lb_c = (t & 31) * 4;
    const float* bp = Bm + (size_t)lb_k * ldb + col0 + lb_c;

    int ty = t >> 4, tx = t & 15;
    float acc[8][8] = {{0.f}};

    float4 av = make_float4(0.f,0.f,0.f,0.f), bv;
    if (a_base >= 0) av = *(const float4*)(A + a_base + la_k);
    bv = *(const float4*)bp;

    for (int k0 = 0; k0 < K; k0 += 8) {
        __syncthreads();
        As[la_k  ][la_r] = av.x;  As[la_k+1][la_r] = av.y;
        As[la_k+2][la_r] = av.z;  As[la_k+3][la_r] = av.w;
        *(float4*)&Bs[lb_k][lb_c] = bv;
        __syncthreads();
        if (k0 + 8 < K) {
            if (a_base >= 0) av = *(const float4*)(A + a_base + k0 + 8 + la_k);
            bv = *(const float4*)(bp + (size_t)(k0 + 8) * ldb);
        }
        #pragma unroll
        for (int kk = 0; kk < 8; kk++) {
            float4 a0 = *(const float4*)&As[kk][ty*8];
            float4 a1 = *(const float4*)&As[kk][ty*8+4];
            float4 b0 = *(const float4*)&Bs[kk][tx*8];
            float4 b1 = *(const float4*)&Bs[kk][tx*8+4];
            float ar[8] = {a0.x,a0.y,a0.z,a0.w,a1.x,a1.y,a1.z,a1.w};
            float br[8] = {b0.x,b0.y,b0.z,b0.w,b1.x,b1.y,b1.z,b1.w};
            #pragma unroll
            for (int i = 0; i < 8; i++)
                #pragma unroll
                for (int j = 0; j < 8; j++)
                    acc[i][j] = fmaf(ar[i], br[j], acc[i][j]);
        }
    }

    #pragma unroll
    for (int i = 0; i < 8; i++) {
        int row = row0 + ty*8 + i;
        if (row < M) {
            #pragma unroll
            for (int jj = 0; jj < 8; jj += 4) {
                int col = col0 + tx*8 + jj;
                float4 v = make_float4(acc[i][jj], acc[i][jj+1], acc[i][jj+2], acc[i][jj+3]);
                *(float4*)&Cm[(size_t)row * ldc + col] = v;
            }
        }
    }
}

// ============ bf16x3 MMA GEMM (m16n8k16 + ldmatrix), 128x128, BK=32 =========
// 8 warps 2(M)x4(N), warp tile 64x32. Error ~2^-17 (post-topk path only).
// EPI: 0 plain, 1 +bias+resid, 2 +bias+GELU. GA: gather A rows; GR: gather resid.
#define LDSM_X4(r0,r1,r2,r3,addr) \
    asm volatile("ldmatrix.sync.aligned.m8n8.x4.shared.b16 {%0,%1,%2,%3},[%4];" \
        : "=r"(r0),"=r"(r1),"=r"(r2),"=r"(r3) : "r"(addr))
#define LDSM_X4T(r0,r1,r2,r3,addr) \
    asm volatile("ldmatrix.sync.aligned.m8n8.x4.trans.shared.b16 {%0,%1,%2,%3},[%4];" \
        : "=r"(r0),"=r"(r1),"=r"(r2),"=r"(r3) : "r"(addr))

__device__ __forceinline__ void mma_bf16(float* c, const uint32_t* a,
                                         uint32_t b0, uint32_t b1) {
    asm volatile(
        "mma.sync.aligned.m16n8k16.row.col.f32.bf16.bf16.f32 "
        "{%0,%1,%2,%3},{%4,%5,%6,%7},{%8,%9},{%0,%1,%2,%3};"
        : "+f"(c[0]), "+f"(c[1]), "+f"(c[2]), "+f"(c[3])
        : "r"(a[0]), "r"(a[1]), "r"(a[2]), "r"(a[3]), "r"(b0), "r"(b1));
}

__device__ __forceinline__ void cvt16(const float* v, uint32_t* uh, uint32_t* ul) {
    #pragma unroll
    for (int p = 0; p < 8; p++) {
        float a = v[2*p], b = v[2*p+1];
        __nv_bfloat16 ha = __float2bfloat16(a), hb = __float2bfloat16(b);
        __nv_bfloat162 hi2; hi2.x = ha; hi2.y = hb;
        __nv_bfloat162 lo2 = __floats2bfloat162_rn(
            a - __bfloat162float(ha), b - __bfloat162float(hb));
        uh[p] = *(uint32_t*)&hi2;
        ul[p] = *(uint32_t*)&lo2;
    }
}

// smem: A rows 128, stride 80B (64B data + 16 pad); B rows 32 (k), stride 272B
#define A_STR 80
#define B_STR 272

template<bool GA, bool GR, int EPI>
__global__ __launch_bounds__(256) void bf_gemm(
    const float* __restrict__ A, int lda,
    const float* __restrict__ Bm, int ldb,
    float* __restrict__ Cm, int ldc,
    int M, int N, int K,
    const float* __restrict__ bias, const float* __restrict__ resid,
    const int* __restrict__ rowmap)
{
    __shared__ __align__(16) char sAh[128*A_STR];
    __shared__ __align__(16) char sAl[128*A_STR];
    __shared__ __align__(16) char sBh[32*B_STR];
    __shared__ __align__(16) char sBl[32*B_STR];

    const int t = threadIdx.x;
    const int lane = t & 31, wid = t >> 5;
    const int lq = lane >> 2, lr = lane & 3;
    const int wm = wid & 1,  wn = wid >> 1;
    const int row0 = blockIdx.y * 128, col0 = blockIdx.x * 128;

    // ---- loader mapping
    const int la_r = t >> 1, la_half = (t & 1);       // A: row, k-half(16)
    const int lb_k = t >> 3, lb_n = (t & 7) * 16;     // B: k-row, n-offset
    long a_base = -1;
    {
        int arow = row0 + la_r;
        if (arow < M) a_base = (long)(GA ? rowmap[arow] : arow) * lda;
    }
    const float* bptr = Bm + (size_t)lb_k * ldb + col0 + lb_n;

    // ---- ldmatrix per-thread addresses
    uint32_t a_h_base, a_l_base, b_h_base, b_l_base;
    {
        uint32_t sa;
        asm("{ .reg .u64 tt; cvta.to.shared.u64 tt, %1; cvt.u32.u64 %0, tt; }"
            : "=r"(sa) : "l"((void*)sAh));
        uint32_t arow = wm*64 + ((lane>>3)&1)*8 + (lane&7);
        uint32_t aoff = arow*A_STR + (lane>>4)*16;
        a_h_base = sa + aoff;
        asm("{ .reg .u64 tt; cvta.to.shared.u64 tt, %1; cvt.u32.u64 %0, tt; }"
            : "=r"(sa) : "l"((void*)sAl));
        a_l_base = sa + aoff;
        uint32_t brow = ((lane>>3)&1)*8 + (lane&7);
        uint32_t boff = brow*B_STR + wn*64 + (lane>>4)*16;
        asm("{ .reg .u64 tt; cvta.to.shared.u64 tt, %1; cvt.u32.u64 %0, tt; }"
            : "=r"(sa) : "l"((void*)sBh));
        b_h_base = sa + boff;
        asm("{ .reg .u64 tt; cvta.to.shared.u64 tt, %1; cvt.u32.u64 %0, tt; }"
            : "=r"(sa) : "l"((void*)sBl));
        b_l_base = sa + boff;
    }

    float acc[4][4][4];
    #pragma unroll
    for (int i = 0; i < 4; i++)
        #pragma unroll
        for (int j = 0; j < 4; j++)
            #pragma unroll
            for (int q = 0; q < 4; q++) acc[i][j][q] = 0.f;

    float av[16], bv[16];
    auto ldg = [&](int kt) {
        int k0 = kt * 32 + la_half * 16;
        if (a_base >= 0) {
            #pragma unroll
            for (int j = 0; j < 4; j++)
                *(float4*)&av[j*4] = *(const float4*)(A + a_base + k0 + j*4);
        } else {
            #pragma unroll
            for (int j = 0; j < 16; j++) av[j] = 0.f;
        }
        const float* bp = bptr + (size_t)(kt*32) * ldb;
        #pragma unroll
        for (int j = 0; j < 4; j++)
            *(float4*)&bv[j*4] = *(const float4*)(bp + j*4);
    };

    const int KT = K >> 5;
    ldg(0);

    for (int kt = 0; kt < KT; ++kt) {
        // store current tile (hi/lo split) to smem
        {
            uint32_t uh[8], ul[8];
            cvt16(av, uh, ul);
            char* pa = sAh + la_r*A_STR + la_half*32;
            *(uint4*)pa        = make_uint4(uh[0],uh[1],uh[2],uh[3]);
            *(uint4*)(pa + 16) = make_uint4(uh[4],uh[5],uh[6],uh[7]);
            pa = sAl + la_r*A_STR + la_half*32;
            *(uint4*)pa        = make_uint4(ul[0],ul[1],ul[2],ul[3]);
            *(uint4*)(pa + 16) = make_uint4(ul[4],ul[5],ul[6],ul[7]);
            cvt16(bv, uh, ul);
            char* pb = sBh + lb_k*B_STR + lb_n*2;
            *(uint4*)pb        = make_uint4(uh[0],uh[1],uh[2],uh[3]);
            *(uint4*)(pb + 16) = make_uint4(uh[4],uh[5],uh[6],uh[7]);
            pb = sBl + lb_k*B_STR + lb_n*2;
            *(uint4*)pb        = make_uint4(ul[0],ul[1],ul[2],ul[3]);
            *(uint4*)(pb + 16) = make_uint4(ul[4],ul[5],ul[6],ul[7]);
        }
        __syncthreads();
        if (kt + 1 < KT) ldg(kt + 1);

        #pragma unroll
        for (int ks = 0; ks < 2; ks++) {
            uint32_t ah[4][4], al_[4][4], bh[4][2], bl_[4][2];
            #pragma unroll
            for (int mf = 0; mf < 4; mf++) {
                uint32_t aa = a_h_base + mf*(16*A_STR) + ks*32;
                LDSM_X4(ah[mf][0],ah[mf][1],ah[mf][2],ah[mf][3], aa);
                aa = a_l_base + mf*(16*A_STR) + ks*32;
                LDSM_X4(al_[mf][0],al_[mf][1],al_[mf][2],al_[mf][3], aa);
            }
            #pragma unroll
            for (int nfp = 0; nfp < 2; nfp++) {
                uint32_t bb = b_h_base + ks*(16*B_STR) + nfp*32;
                LDSM_X4T(bh[2*nfp][0], bh[2*nfp][1], bh[2*nfp+1][0], bh[2*nfp+1][1], bb);
                bb = b_l_base + ks*(16*B_STR) + nfp*32;
                LDSM_X4T(bl_[2*nfp][0], bl_[2*nfp][1], bl_[2*nfp+1][0], bl_[2*nfp+1][1], bb);
            }
            #pragma unroll
            for (int mf = 0; mf < 4; mf++)
                #pragma unroll
                for (int nf = 0; nf < 4; nf++) {
                    float* c = acc[mf][nf];
                    mma_bf16(c, ah[mf],  bh[nf][0],  bh[nf][1]);
                    mma_bf16(c, ah[mf],  bl_[nf][0], bl_[nf][1]);
                    mma_bf16(c, al_[mf], bh[nf][0],  bh[nf][1]);
                }
        }
        __syncthreads();
    }

    // ---- epilogue (same fragment layout as m16n8 tf32 version)
    #pragma unroll
    for (int mf = 0; mf < 4; mf++) {
        int rbase = row0 + wm*64 + mf*16 + lq;
        #pragma unroll
        for (int half = 0; half < 2; half++) {
            int row = rbase + half*8;
            if (row < M) {
                long rres = 0;
                if (EPI == 1) rres = (long)(GR ? rowmap[row] : row) * N;
                #pragma unroll
                for (int nf = 0; nf < 4; nf++) {
                    int col = col0 + wn*32 + nf*8 + lr*2;
                    float v0 = acc[mf][nf][half*2+0];
                    float v1 = acc[mf][nf][half*2+1];
                    if (EPI != 0) { v0 += bias[col]; v1 += bias[col+1]; }
                    if (EPI == 2) { v0 = gelu_exact(v0); v1 = gelu_exact(v1); }
                    if (EPI == 1) { v0 += resid[rres+col]; v1 += resid[rres+col+1]; }
                    *(float2*)&Cm[(size_t)row * ldc + col] = make_float2(v0, v1);
                }
            }
        }
    }
}

// ------------- cls attention row (q0 = xn0 @ Wq, softmax, -> CLSH) ----------
__global__ __launch_bounds__(256) void cls_kernel(
    const float* __restrict__ XN, const float* __restrict__ wqkv,
    const float* __restrict__ QKV, const float* __restrict__ amask,
    float* __restrict__ CLSH)
{
    __shared__ float q0[64];
    __shared__ float sS[1024];
    __shared__ float red[8];
    int h = blockIdx.x, b = blockIdx.y, t = threadIdx.x;

    {
        int d = t >> 2, part = t & 3;
        const float* xr = XN + (size_t)b * N_ * C_;
        const float* wc = wqkv + h*64 + d;
        float s = 0.f;
        int k0 = part * 192;
        for (int k = k0; k < k0 + 192; k++)
            s = fmaf(xr[k], wc[(size_t)k * 2304], s);
        s += __shfl_xor_sync(~0u, s, 1);
        s += __shfl_xor_sync(~0u, s, 2);
        if (part == 0) q0[d] = s;
    }
    __syncthreads();

    float sv[4];
    #pragma unroll
    for (int j = 0; j < 4; j++) {
        int m = t + 256*j;
        const float* kr = QKV + (size_t)(b*N_ + m)*2304 + 768 + h*64;
        float acc = 0.f;
        #pragma unroll
        for (int d = 0; d < 64; d++) acc = fmaf(q0[d], kr[d], acc);
        sv[j] = acc * 0.125f;
    }
    float mx = fmaxf(fmaxf(sv[0], sv[1]), fmaxf(sv[2], sv[3]));
    #pragma unroll
    for (int o = 16; o; o >>= 1) mx = fmaxf(mx, __shfl_xor_sync(~0u, mx, o));
    if ((t & 31) == 0) red[t >> 5] = mx;
    __syncthreads();
    mx = red[0];
    #pragma unroll
    for (int i = 1; i < 8; i++) mx = fmaxf(mx, red[i]);

    const float* mrow = amask + (size_t)b * N_ * N_;
    float sum = 0.f;
    #pragma unroll
    for (int j = 0; j < 4; j++) {
        int m = t + 256*j;
        float e = expf(sv[j] - mx) * mrow[m];
        sS[m] = e;
        sum += e;
    }
    #pragma unroll
    for (int o = 16; o; o >>= 1) sum += __shfl_xor_sync(~0u, sum, o);
    __syncthreads();
    if ((t & 31) == 0) red[t >> 5] = sum;
    __syncthreads();
    sum = 0.f;
    #pragma unroll
    for (int i = 0; i < 8; i++) sum += red[i];
    float rinv = 1.0f / (sum + 1e-6f);
    const float epsn = 1e-6f / 1024.0f;
    float* cl = CLSH + (size_t)(b*H_ + h) * (N_ - 1);
    #pragma unroll
    for (int j = 0; j < 4; j++) {
        int m = t + 256*j;
        if (m >= 1) cl[m-1] = (sS[m] + epsn) * rinv;
    }
}

// --------- Attention for SELECTED rows: block = (32 compact rows, h, b) -----
__global__ __launch_bounds__(256) void attn_sel_kernel(
    const float* __restrict__ QG, const float* __restrict__ QKV,
    const float* __restrict__ amask, const int* __restrict__ ROWSEL,
    float* __restrict__ XATT)
{
    extern __shared__ float smx[];
    float* sS  = smx;                 // 32*1024
    float* sQt = smx + 32*1024;       // [64][36]
    float* sT  = sQt + 64*36;         // 8448 floats
    int t = threadIdx.x;
    int n0 = blockIdx.x * 32, h = blockIdx.y, b = blockIdx.z;
    size_t base_bh = (size_t)b * N_ * 2304 + (size_t)h * 64;

    for (int e = t; e < 32*64; e += 256) {
        int i = e >> 6, d = e & 63;
        int r = n0 + i;
        sQt[d*36 + i] = (r < RN_)
            ? QG[(size_t)(b*RN_ + r) * C_ + h*64 + d] : 0.f;
    }

    int ty = t >> 5, tx = t & 31;

    for (int kt = 0; kt < 8; kt++) {
        int m0 = kt << 7;
        __syncthreads();
        for (int e = t; e < 128*64; e += 256) {
            int m = e >> 6, d = e & 63;
            sT[d*132 + m] = QKV[base_bh + 768 + (size_t)(m0 + m) * 2304 + d];
        }
        __syncthreads();
        float acc[4][4] = {{0.f}};
        #pragma unroll 4
        for (int d = 0; d < 64; d++) {
            float4 aq = *(const float4*)&sQt[d*36 + ty*4];
            float4 bk = *(const float4*)&sT[d*132 + tx*4];
            float ar[4] = {aq.x,aq.y,aq.z,aq.w};
            float br[4] = {bk.x,bk.y,bk.z,bk.w};
            #pragma unroll
            for (int i = 0; i < 4; i++)
                #pragma unroll
                for (int j = 0; j < 4; j++)
                    acc[i][j] = fmaf(ar[i], br[j], acc[i][j]);
        }
        #pragma unroll
        for (int i = 0; i < 4; i++) {
            float4 v = make_float4(acc[i][0]*0.125f, acc[i][1]*0.125f,
                                   acc[i][2]*0.125f, acc[i][3]*0.125f);
            *(float4*)&sS[(ty*4+i)*1024 + m0 + tx*4] = v;
        }
    }
    __syncthreads();

    int lane = t & 31, w = t >> 5;
    for (int rr = 0; rr < 4; rr++) {
        int i = w + rr*8;
        int r = n0 + i;
        if (r >= RN_) continue;
        int norig = ROWSEL[b*RN_ + r] - b*1024;
        float* row = sS + i*1024;
        float mx = -3.4e38f;
        for (int m = lane; m < 1024; m += 32) mx = fmaxf(mx, row[m]);
        #pragma unroll
        for (int o = 16; o; o >>= 1) mx = fmaxf(mx, __shfl_xor_sync(~0u, mx, o));
        const float* mrow = amask + (size_t)(b * N_ + norig) * N_;
        float sum = 0.f;
        for (int m = lane; m < 1024; m += 32) {
            float e = expf(row[m] - mx) * mrow[m];
            row[m] = e;
            sum += e;
        }
        #pragma unroll
        for (int o = 16; o; o >>= 1) sum += __shfl_xor_sync(~0u, sum, o);
        float rinv = 1.0f / (sum + 1e-6f);
        const float epsn = 1e-6f / 1024.0f;
        for (int m = lane; m < 1024; m += 32) row[m] = (row[m] + epsn) * rinv;
    }
    __syncthreads();

    float oacc[4][2] = {{0.f}};
    for (int vt = 0; vt < 8; vt++) {
        int m0 = vt << 7;
        __syncthreads();
        for (int e = t; e < 128*64; e += 256) {
            int m = e >> 6, d = e & 63;
            sT[m*66 + d] = QKV[base_bh + 1536 + (size_t)(m0 + m) * 2304 + d];
        }
        __syncthreads();
        #pragma unroll 4
        for (int m = 0; m < 128; m++) {
            float2 vv = *(const float2*)&sT[m*66 + tx*2];
            #pragma unroll
            for (int i = 0; i < 4; i++) {
                float a = sS[(ty*4+i)*1024 + m0 + m];
                oacc[i][0] = fmaf(a, vv.x, oacc[i][0]);
                oacc[i][1] = fmaf(a, vv.y, oacc[i][1]);
            }
        }
    }
    #pragma unroll
    for (int i = 0; i < 4; i++) {
        int r = n0 + ty*4 + i;
        if (r < RN_) {
            float2 o2 = make_float2(oacc[i][0], oacc[i][1]);
            *(float2*)&XATT[(size_t)(b*RN_ + r) * C_ + h*64 + tx*2] = o2;
        }
    }
}

// ---------------- top-k via bitonic sort (jax.lax.top_k semantics) ----------
__global__ __launch_bounds__(256) void topk_kernel(
    const float* __restrict__ CLSH, int* __restrict__ ROWSEL,
    float* __restrict__ outIA, float* __restrict__ outIM)
{
    __shared__ float sv[1024];
    __shared__ int   si[1024];
    int seg = blockIdx.x, b = blockIdx.y, t = threadIdx.x;
    int P     = seg ? 1024 : 256;
    int count = seg ? 768  : 255;
    int base  = seg ? 255  : 0;

    for (int e = t; e < P; e += 256) {
        if (e < count) {
            float s = 0.f;
            #pragma unroll
            for (int hh = 0; hh < 12; hh++)
                s += CLSH[(size_t)(b*12 + hh) * 1023 + base + e];
            sv[e] = s;
            si[e] = e;
        } else { sv[e] = -3.4e38f; si[e] = 0x7FFFFFFF; }
    }

    for (int k = 2; k <= P; k <<= 1)
        for (int j = k >> 1; j > 0; j >>= 1) {
            __syncthreads();
            for (int i = t; i < P; i += 256) {
                int ixj = i ^ j;
                if (ixj > i) {
                    float v1 = sv[i], v2 = sv[ixj];
                    int a1 = si[i], a2 = si[ixj];
                    bool before12 = (v1 > v2) || (v1 == v2 && a1 < a2);
                    bool up = ((i & k) == 0);
                    if (up != before12) {
                        sv[i] = v2; sv[ixj] = v1; si[i] = a2; si[ixj] = a1;
                    }
                }
            }
        }
    __syncthreads();

    if (seg == 0) {
        if (t < 128) {
            int idx = si[t];
            if (outIA) outIA[b*128 + t] = (float)idx;
            ROWSEL[b*513 + 1 + t] = b*1024 + 1 + idx;
        }
        if (t == 0) ROWSEL[b*513] = b*1024;
    } else {
        for (int e = t; e < 384; e += 256) {
            int idx = si[e];
            if (outIM) outIM[b*384 + e] = (float)idx;
            ROWSEL[b*513 + 129 + e] = b*1024 + 256 + idx;
        }
    }
}

__global__ void fill_ones(float* __restrict__ p, int n) {
    int i = blockIdx.x * 256 + threadIdx.x;
    if (i < n) p[i] = 1.0f;
}

// ---------------- launcher ----------------
extern "C" void kernel_launch(void* const* d_in, const int* in_sizes, int n_in,
                              void* d_out, int out_size)
{
    const float* x      = (const float*)d_in[0];
    const float* amask  = (const float*)d_in[1];
    const float* w_qkv  = (const float*)d_in[4];
    const float* w_proj = (const float*)d_in[5];
    const float* b_proj = (const float*)d_in[6];
    const float* g1     = (const float*)d_in[7];
    const float* b1     = (const float*)d_in[8];
    const float* g2     = (const float*)d_in[9];
    const float* b2     = (const float*)d_in[10];
    const float* w_fc1  = (const float*)d_in[11];
    const float* b_fc1  = (const float*)d_in[12];
    const float* w_fc2  = (const float*)d_in[13];
    const float* b_fc2  = (const float*)d_in[14];
    float* out = (float*)d_out;

    float *XN, *QKV, *QG, *XATT, *CLSH, *XP, *XN2, *HB; int* ROWSEL;
    cudaGetSymbolAddress((void**)&XN,   g_XN);
    cudaGetSymbolAddress((void**)&QKV,  g_QKV);
    cudaGetSymbolAddress((void**)&QG,   g_QG);
    cudaGetSymbolAddress((void**)&XATT, g_XATT);
    cudaGetSymbolAddress((void**)&CLSH, g_CLSH);
    cudaGetSymbolAddress((void**)&XP,   g_XP);
    cudaGetSymbolAddress((void**)&XN2,  g_XN2);
    cudaGetSymbolAddress((void**)&HB,   g_HB);
    cudaGetSymbolAddress((void**)&ROWSEL, g_ROWSEL);

    const int ATTN_SMEM = (32*1024 + 64*36 + 8448) * 4;  // 174080 B
    cudaFuncSetAttribute(attn_sel_kernel,
        cudaFuncAttributeMaxDynamicSharedMemorySize, ATTN_SMEM);

    const int OFF_IA = 8*513*768;
    const int OFF_IM = OFF_IA + 8*128;
    const int OFF_MK = OFF_IM + 8*384;
    const int MK_SZ  = 8*513*513;
    const int TOTAL  = OFF_MK + MK_SZ;
    float* outIA = (out_size >= TOTAL) ? out + OFF_IA : nullptr;
    float* outIM = (out_size >= TOTAL) ? out + OFF_IM : nullptr;

    // 1. LN1 (all rows)
    ln_kernel<<<B_*N_, 256>>>(x, g1, b1, XN);
    // 2a. K GEMM (fp32 EXACT — feeds cls scores -> top-k). Same column-block
    //     decomposition as R10 => bit-identical K.
    sgemm2<false><<<dim3(6, 64), 256>>>(
        XN, C_, w_qkv + 768, 3*C_, QKV + 768, 3*C_, B_*N_, C_, C_, nullptr);
    // 2b. V GEMM (bf16x3 mma — feeds AV only, tolerant)
    bf_gemm<false,false,0><<<dim3(6, 64), 256>>>(
        XN, C_, w_qkv + 1536, 3*C_, QKV + 1536, 3*C_, B_*N_, C_, C_,
        nullptr, nullptr, nullptr);
    // 3. cls attention row (fp32) -> CLSH
    cls_kernel<<<dim3(H_, B_), 256>>>(XN, w_qkv, QKV, amask, CLSH);
    // 4. top-k -> ROWSEL + idx outputs
    topk_kernel<<<dim3(2, B_), 256>>>(CLSH, ROWSEL, outIA, outIM);
    // 5. gathered Q GEMM (bf16x3): QG = XN[sel] @ w_qkv[:,0:768]
    bf_gemm<true,false,0><<<dim3(6, 33), 256>>>(
        XN, C_, w_qkv, 3*C_, QG, C_, MROWS, C_, C_, nullptr, nullptr, ROWSEL);
    // 6. attention for selected rows only (fp32 SIMT)
    attn_sel_kernel<<<dim3((RN_+31)/32, H_, B_), 256, ATTN_SMEM>>>(
        QG, QKV, amask, ROWSEL, XATT);
    // 7. proj (bf16x3): XP = x[sel] + (XATT @ w_proj + b_proj)
    bf_gemm<false,true,1><<<dim3(6, 33), 256>>>(
        XATT, C_, w_proj, C_, XP, C_, MROWS, C_, C_, b_proj, x, ROWSEL);
    // 8. LN2
    ln_kernel<<<MROWS, 256>>>(XP, g2, b2, XN2);
    // 9. fc1 + GELU (bf16x3)
    bf_gemm<false,false,2><<<dim3(24, 33), 256>>>(
        XN2, C_, w_fc1, HID_, HB, HID_, MROWS, HID_, C_, b_fc1, nullptr, nullptr);
    // 10. fc2 + bias + residual -> d_out (bf16x3)
    bf_gemm<false,false,1><<<dim3(6, 33), 256>>>(
        HB, HID_, w_fc2, C_, out, C_, MROWS, C_, HID_, b_fc2, XP, nullptr);
    // 11. new_mask == all ones (proved in R4)
    if (out_size >= TOTAL)
        fill_ones<<<(MK_SZ + 255)/256, 256>>>(out + OFF_MK, MK_SZ);
}

// round 12
// speedup vs baseline: 1.8050x; 1.0071x over previous
#include <cuda_runtime.h>
#include <cuda_bf16.h>
#include <cstdint>
#include <math.h>

#define B_   8
#define N_   1024
#define C_   768
#define H_   12
#define HID_ 3072
#define RN_  513
#define MROWS (B_*RN_)   // 4104

// ---------------- scratch (static __device__, no allocation) ----------------
__device__ float g_XN  [B_*N_*C_];
__device__ float g_QKV [B_*N_*3*C_];   // K,V region (cols 768..2303) used
__device__ float g_QG  [MROWS*C_];
__device__ float g_XATT[MROWS*C_];
__device__ float g_CLSH[B_*H_*(N_-1)];
__device__ int   g_ROWSEL[B_*RN_];
__device__ float g_XP  [MROWS*C_];
__device__ float g_XN2 [MROWS*C_];
__device__ float g_HB  [MROWS*HID_];

__device__ __forceinline__ float gelu_exact(float v) {
    return 0.5f * v * (1.0f + erff(v * 0.70710678118654752f));
}

// ---------------- LayerNorm (1 row / block, C=768, 256 threads) -------------
__global__ __launch_bounds__(256) void ln_kernel(
    const float* __restrict__ X, const float* __restrict__ g,
    const float* __restrict__ bt, float* __restrict__ Y)
{
    __shared__ float red[8];
    int row = blockIdx.x, t = threadIdx.x;
    const float* xr = X + (size_t)row * C_;
    float x0 = xr[t], x1 = xr[t+256], x2 = xr[t+512];
    float s = x0 + x1 + x2;
    #pragma unroll
    for (int o = 16; o; o >>= 1) s += __shfl_xor_sync(~0u, s, o);
    if ((t & 31) == 0) red[t >> 5] = s;
    __syncthreads();
    float tot = 0.f;
    #pragma unroll
    for (int i = 0; i < 8; i++) tot += red[i];
    float mean = tot * (1.0f/768.0f);
    __syncthreads();
    float d0 = x0-mean, d1 = x1-mean, d2 = x2-mean;
    float q = d0*d0 + d1*d1 + d2*d2;
    #pragma unroll
    for (int o = 16; o; o >>= 1) q += __shfl_xor_sync(~0u, q, o);
    if ((t & 31) == 0) red[t >> 5] = q;
    __syncthreads();
    float tq = 0.f;
    #pragma unroll
    for (int i = 0; i < 8; i++) tq += red[i];
    float rstd = 1.0f / sqrtf(tq * (1.0f/768.0f) + 1e-5f);
    float* yr = Y + (size_t)row * C_;
    yr[t]     = d0*rstd*g[t]     + bt[t];
    yr[t+256] = d1*rstd*g[t+256] + bt[t+256];
    yr[t+512] = d2*rstd*g[t+512] + bt[t+512];
}

// ------- fp32 SGEMM w/ strides (exact path for K): 128x128x8, 8x8 ----------
template<bool GATHER>
__global__ __launch_bounds__(256) void sgemm2(
    const float* __restrict__ A, int lda,
    const float* __restrict__ Bm, int ldb,
    float* __restrict__ Cm, int ldc,
    int M, int N, int K, const int* __restrict__ rowmap)
{
    __shared__ float As[8][128];
    __shared__ float Bs[8][128];
    int t = threadIdx.x;
    int row0 = blockIdx.y * 128, col0 = blockIdx.x * 128;

    int la_r = t >> 1, la_k = (t & 1) * 4;
    long a_base = -1;
    {
        int arow = row0 + la_r;
        if (arow < M) a_base = (long)(GATHER ? rowmap[arow] : arow) * lda;
    }
    int lb_k = t >> 5, lb_c = (t & 31) * 4;
    const float* bp = Bm + (size_t)lb_k * ldb + col0 + lb_c;

    int ty = t >> 4, tx = t & 15;
    float acc[8][8] = {{0.f}};

    float4 av = make_float4(0.f,0.f,0.f,0.f), bv;
    if (a_base >= 0) av = *(const float4*)(A + a_base + la_k);
    bv = *(const float4*)bp;

    for (int k0 = 0; k0 < K; k0 += 8) {
        __syncthreads();
        As[la_k  ][la_r] = av.x;  As[la_k+1][la_r] = av.y;
        As[la_k+2][la_r] = av.z;  As[la_k+3][la_r] = av.w;
        *(float4*)&Bs[lb_k][lb_c] = bv;
        __syncthreads();
        if (k0 + 8 < K) {
            if (a_base >= 0) av = *(const float4*)(A + a_base + k0 + 8 + la_k);
            bv = *(const float4*)(bp + (size_t)(k0 + 8) * ldb);
        }
        #pragma unroll
        for (int kk = 0; kk < 8; kk++) {
            float4 a0 = *(const float4*)&As[kk][ty*8];
            float4 a1 = *(const float4*)&As[kk][ty*8+4];
            float4 b0 = *(const float4*)&Bs[kk][tx*8];
            float4 b1 = *(const float4*)&Bs[kk][tx*8+4];
            float ar[8] = {a0.x,a0.y,a0.z,a0.w,a1.x,a1.y,a1.z,a1.w};
            float br[8] = {b0.x,b0.y,b0.z,b0.w,b1.x,b1.y,b1.z,b1.w};
            #pragma unroll
            for (int i = 0; i < 8; i++)
                #pragma unroll
                for (int j = 0; j < 8; j++)
                    acc[i][j] = fmaf(ar[i], br[j], acc[i][j]);
        }
    }

    #pragma unroll
    for (int i = 0; i < 8; i++) {
        int row = row0 + ty*8 + i;
        if (row < M) {
            #pragma unroll
            for (int jj = 0; jj < 8; jj += 4) {
                int col = col0 + tx*8 + jj;
                float4 v = make_float4(acc[i][jj], acc[i][jj+1], acc[i][jj+2], acc[i][jj+3]);
                *(float4*)&Cm[(size_t)row * ldc + col] = v;
            }
        }
    }
}

// ============ bf16x3 MMA GEMM (m16n8k16 + ldmatrix), 128x128, BK=32 =========
// 8 warps 2(M)x4(N), warp tile 64x32. Error ~2^-17 (post-topk path only).
// EPI: 0 plain, 1 +bias+resid, 2 +bias+GELU. GA: gather A rows; GR: gather resid.
#define LDSM_X4(r0,r1,r2,r3,addr) \
    asm volatile("ldmatrix.sync.aligned.m8n8.x4.shared.b16 {%0,%1,%2,%3},[%4];" \
        : "=r"(r0),"=r"(r1),"=r"(r2),"=r"(r3) : "r"(addr))
#define LDSM_X4T(r0,r1,r2,r3,addr) \
    asm volatile("ldmatrix.sync.aligned.m8n8.x4.trans.shared.b16 {%0,%1,%2,%3},[%4];" \
        : "=r"(r0),"=r"(r1),"=r"(r2),"=r"(r3) : "r"(addr))

__device__ __forceinline__ void mma_bf16(float* c, const uint32_t* a,
                                         uint32_t b0, uint32_t b1) {
    asm volatile(
        "mma.sync.aligned.m16n8k16.row.col.f32.bf16.bf16.f32 "
        "{%0,%1,%2,%3},{%4,%5,%6,%7},{%8,%9},{%0,%1,%2,%3};"
        : "+f"(c[0]), "+f"(c[1]), "+f"(c[2]), "+f"(c[3])
        : "r"(a[0]), "r"(a[1]), "r"(a[2]), "r"(a[3]), "r"(b0), "r"(b1));
}

__device__ __forceinline__ void cvt16(const float* v, uint32_t* uh, uint32_t* ul) {
    #pragma unroll
    for (int p = 0; p < 8; p++) {
        float a = v[2*p], b = v[2*p+1];
        __nv_bfloat16 ha = __float2bfloat16(a), hb = __float2bfloat16(b);
        __nv_bfloat162 hi2; hi2.x = ha; hi2.y = hb;
        __nv_bfloat162 lo2 = __floats2bfloat162_rn(
            a - __bfloat162float(ha), b - __bfloat162float(hb));
        uh[p] = *(uint32_t*)&hi2;
        ul[p] = *(uint32_t*)&lo2;
    }
}

// smem: A rows 128, stride 80B (64B data + 16 pad); B rows 32 (k), stride 272B
#define A_STR 80
#define B_STR 272

template<bool GA, bool GR, int EPI>
__global__ __launch_bounds__(256) void bf_gemm(
    const float* __restrict__ A, int lda,
    const float* __restrict__ Bm, int ldb,
    float* __restrict__ Cm, int ldc,
    int M, int N, int K,
    const float* __restrict__ bias, const float* __restrict__ resid,
    const int* __restrict__ rowmap)
{
    __shared__ __align__(16) char sAh[128*A_STR];
    __shared__ __align__(16) char sAl[128*A_STR];
    __shared__ __align__(16) char sBh[32*B_STR];
    __shared__ __align__(16) char sBl[32*B_STR];

    const int t = threadIdx.x;
    const int lane = t & 31, wid = t >> 5;
    const int lq = lane >> 2, lr = lane & 3;
    const int wm = wid & 1,  wn = wid >> 1;
    const int row0 = blockIdx.y * 128, col0 = blockIdx.x * 128;

    // ---- loader mapping
    const int la_r = t >> 1, la_half = (t & 1);       // A: row, k-half(16)
    const int lb_k = t >> 3, lb_n = (t & 7) * 16;     // B: k-row, n-offset
    long a_base = -1;
    {
        int arow = row0 + la_r;
        if (arow < M) a_base = (long)(GA ? rowmap[arow] : arow) * lda;
    }
    const float* bptr = Bm + (size_t)lb_k * ldb + col0 + lb_n;

    // ---- ldmatrix per-thread addresses
    uint32_t a_h_base, a_l_base, b_h_base, b_l_base;
    {
        uint32_t sa;
        asm("{ .reg .u64 tt; cvta.to.shared.u64 tt, %1; cvt.u32.u64 %0, tt; }"
            : "=r"(sa) : "l"((void*)sAh));
        uint32_t arow = wm*64 + ((lane>>3)&1)*8 + (lane&7);
        uint32_t aoff = arow*A_STR + (lane>>4)*16;
        a_h_base = sa + aoff;
        asm("{ .reg .u64 tt; cvta.to.shared.u64 tt, %1; cvt.u32.u64 %0, tt; }"
            : "=r"(sa) : "l"((void*)sAl));
        a_l_base = sa + aoff;
        uint32_t brow = ((lane>>3)&1)*8 + (lane&7);
        uint32_t boff = brow*B_STR + wn*64 + (lane>>4)*16;
        asm("{ .reg .u64 tt; cvta.to.shared.u64 tt, %1; cvt.u32.u64 %0, tt; }"
            : "=r"(sa) : "l"((void*)sBh));
        b_h_base = sa + boff;
        asm("{ .reg .u64 tt; cvta.to.shared.u64 tt, %1; cvt.u32.u64 %0, tt; }"
            : "=r"(sa) : "l"((void*)sBl));
        b_l_base = sa + boff;
    }

    float acc[4][4][4];
    #pragma unroll
    for (int i = 0; i < 4; i++)
        #pragma unroll
        for (int j = 0; j < 4; j++)
            #pragma unroll
            for (int q = 0; q < 4; q++) acc[i][j][q] = 0.f;

    float av[16], bv[16];
    auto ldg = [&](int kt) {
        int k0 = kt * 32 + la_half * 16;
        if (a_base >= 0) {
            #pragma unroll
            for (int j = 0; j < 4; j++)
                *(float4*)&av[j*4] = *(const float4*)(A + a_base + k0 + j*4);
        } else {
            #pragma unroll
            for (int j = 0; j < 16; j++) av[j] = 0.f;
        }
        const float* bp = bptr + (size_t)(kt*32) * ldb;
        #pragma unroll
        for (int j = 0; j < 4; j++)
            *(float4*)&bv[j*4] = *(const float4*)(bp + j*4);
    };

    const int KT = K >> 5;
    ldg(0);

    for (int kt = 0; kt < KT; ++kt) {
        // store current tile (hi/lo split) to smem
        {
            uint32_t uh[8], ul[8];
            cvt16(av, uh, ul);
            char* pa = sAh + la_r*A_STR + la_half*32;
            *(uint4*)pa        = make_uint4(uh[0],uh[1],uh[2],uh[3]);
            *(uint4*)(pa + 16) = make_uint4(uh[4],uh[5],uh[6],uh[7]);
            pa = sAl + la_r*A_STR + la_half*32;
            *(uint4*)pa        = make_uint4(ul[0],ul[1],ul[2],ul[3]);
            *(uint4*)(pa + 16) = make_uint4(ul[4],ul[5],ul[6],ul[7]);
            cvt16(bv, uh, ul);
            char* pb = sBh + lb_k*B_STR + lb_n*2;
            *(uint4*)pb        = make_uint4(uh[0],uh[1],uh[2],uh[3]);
            *(uint4*)(pb + 16) = make_uint4(uh[4],uh[5],uh[6],uh[7]);
            pb = sBl + lb_k*B_STR + lb_n*2;
            *(uint4*)pb        = make_uint4(ul[0],ul[1],ul[2],ul[3]);
            *(uint4*)(pb + 16) = make_uint4(ul[4],ul[5],ul[6],ul[7]);
        }
        __syncthreads();
        if (kt + 1 < KT) ldg(kt + 1);

        #pragma unroll
        for (int ks = 0; ks < 2; ks++) {
            uint32_t ah[4][4], al_[4][4], bh[4][2], bl_[4][2];
            #pragma unroll
            for (int mf = 0; mf < 4; mf++) {
                uint32_t aa = a_h_base + mf*(16*A_STR) + ks*32;
                LDSM_X4(ah[mf][0],ah[mf][1],ah[mf][2],ah[mf][3], aa);
                aa = a_l_base + mf*(16*A_STR) + ks*32;
                LDSM_X4(al_[mf][0],al_[mf][1],al_[mf][2],al_[mf][3], aa);
            }
            #pragma unroll
            for (int nfp = 0; nfp < 2; nfp++) {
                uint32_t bb = b_h_base + ks*(16*B_STR) + nfp*32;
                LDSM_X4T(bh[2*nfp][0], bh[2*nfp][1], bh[2*nfp+1][0], bh[2*nfp+1][1], bb);
                bb = b_l_base + ks*(16*B_STR) + nfp*32;
                LDSM_X4T(bl_[2*nfp][0], bl_[2*nfp][1], bl_[2*nfp+1][0], bl_[2*nfp+1][1], bb);
            }
            #pragma unroll
            for (int mf = 0; mf < 4; mf++)
                #pragma unroll
                for (int nf = 0; nf < 4; nf++) {
                    float* c = acc[mf][nf];
                    mma_bf16(c, ah[mf],  bh[nf][0],  bh[nf][1]);
                    mma_bf16(c, ah[mf],  bl_[nf][0], bl_[nf][1]);
                    mma_bf16(c, al_[mf], bh[nf][0],  bh[nf][1]);
                }
        }
        __syncthreads();
    }

    // ---- epilogue (same fragment layout as m16n8 tf32 version)
    #pragma unroll
    for (int mf = 0; mf < 4; mf++) {
        int rbase = row0 + wm*64 + mf*16 + lq;
        #pragma unroll
        for (int half = 0; half < 2; half++) {
            int row = rbase + half*8;
            if (row < M) {
                long rres = 0;
                if (EPI == 1) rres = (long)(GR ? rowmap[row] : row) * N;
                #pragma unroll
                for (int nf = 0; nf < 4; nf++) {
                    int col = col0 + wn*32 + nf*8 + lr*2;
                    float v0 = acc[mf][nf][half*2+0];
                    float v1 = acc[mf][nf][half*2+1];
                    if (EPI != 0) { v0 += bias[col]; v1 += bias[col+1]; }
                    if (EPI == 2) { v0 = gelu_exact(v0); v1 = gelu_exact(v1); }
                    if (EPI == 1) { v0 += resid[rres+col]; v1 += resid[rres+col+1]; }
                    *(float2*)&Cm[(size_t)row * ldc + col] = make_float2(v0, v1);
                }
            }
        }
    }
}

// ------------- cls attention row (q0 = xn0 @ Wq, softmax, -> CLSH) ----------
__global__ __launch_bounds__(256) void cls_kernel(
    const float* __restrict__ XN, const float* __restrict__ wqkv,
    const float* __restrict__ QKV, const float* __restrict__ amask,
    float* __restrict__ CLSH)
{
    __shared__ float q0[64];
    __shared__ float sS[1024];
    __shared__ float red[8];
    int h = blockIdx.x, b = blockIdx.y, t = threadIdx.x;

    {
        int d = t >> 2, part = t & 3;
        const float* xr = XN + (size_t)b * N_ * C_;
        const float* wc = wqkv + h*64 + d;
        float s = 0.f;
        int k0 = part * 192;
        for (int k = k0; k < k0 + 192; k++)
            s = fmaf(xr[k], wc[(size_t)k * 2304], s);
        s += __shfl_xor_sync(~0u, s, 1);
        s += __shfl_xor_sync(~0u, s, 2);
        if (part == 0) q0[d] = s;
    }
    __syncthreads();

    float sv[4];
    #pragma unroll
    for (int j = 0; j < 4; j++) {
        int m = t + 256*j;
        const float* kr = QKV + (size_t)(b*N_ + m)*2304 + 768 + h*64;
        float acc = 0.f;
        #pragma unroll
        for (int d = 0; d < 64; d++) acc = fmaf(q0[d], kr[d], acc);
        sv[j] = acc * 0.125f;
    }
    float mx = fmaxf(fmaxf(sv[0], sv[1]), fmaxf(sv[2], sv[3]));
    #pragma unroll
    for (int o = 16; o; o >>= 1) mx = fmaxf(mx, __shfl_xor_sync(~0u, mx, o));
    if ((t & 31) == 0) red[t >> 5] = mx;
    __syncthreads();
    mx = red[0];
    #pragma unroll
    for (int i = 1; i < 8; i++) mx = fmaxf(mx, red[i]);

    const float* mrow = amask + (size_t)b * N_ * N_;
    float sum = 0.f;
    #pragma unroll
    for (int j = 0; j < 4; j++) {
        int m = t + 256*j;
        float e = expf(sv[j] - mx) * mrow[m];
        sS[m] = e;
        sum += e;
    }
    #pragma unroll
    for (int o = 16; o; o >>= 1) sum += __shfl_xor_sync(~0u, sum, o);
    __syncthreads();
    if ((t & 31) == 0) red[t >> 5] = sum;
    __syncthreads();
    sum = 0.f;
    #pragma unroll
    for (int i = 0; i < 8; i++) sum += red[i];
    float rinv = 1.0f / (sum + 1e-6f);
    const float epsn = 1e-6f / 1024.0f;
    float* cl = CLSH + (size_t)(b*H_ + h) * (N_ - 1);
    #pragma unroll
    for (int j = 0; j < 4; j++) {
        int m = t + 256*j;
        if (m >= 1) cl[m-1] = (sS[m] + epsn) * rinv;
    }
}

// --------- Attention for SELECTED rows: block = (32 compact rows, h, b) -----
__global__ __launch_bounds__(256) void attn_sel_kernel(
    const float* __restrict__ QG, const float* __restrict__ QKV,
    const float* __restrict__ amask, const int* __restrict__ ROWSEL,
    float* __restrict__ XATT)
{
    extern __shared__ float smx[];
    float* sS  = smx;                 // 32*1024
    float* sQt = smx + 32*1024;       // [64][36]
    float* sT  = sQt + 64*36;         // 8448 floats
    int t = threadIdx.x;
    int n0 = blockIdx.x * 32, h = blockIdx.y, b = blockIdx.z;
    size_t base_bh = (size_t)b * N_ * 2304 + (size_t)h * 64;

    for (int e = t; e < 32*64; e += 256) {
        int i = e >> 6, d = e & 63;
        int r = n0 + i;
        sQt[d*36 + i] = (r < RN_)
            ? QG[(size_t)(b*RN_ + r) * C_ + h*64 + d] : 0.f;
    }

    int ty = t >> 5, tx = t & 31;

    for (int kt = 0; kt < 8; kt++) {
        int m0 = kt << 7;
        __syncthreads();
        for (int e = t; e < 128*64; e += 256) {
            int m = e >> 6, d = e & 63;
            sT[d*132 + m] = QKV[base_bh + 768 + (size_t)(m0 + m) * 2304 + d];
        }
        __syncthreads();
        float acc[4][4] = {{0.f}};
        #pragma unroll 4
        for (int d = 0; d < 64; d++) {
            float4 aq = *(const float4*)&sQt[d*36 + ty*4];
            float4 bk = *(const float4*)&sT[d*132 + tx*4];
            float ar[4] = {aq.x,aq.y,aq.z,aq.w};
            float br[4] = {bk.x,bk.y,bk.z,bk.w};
            #pragma unroll
            for (int i = 0; i < 4; i++)
                #pragma unroll
                for (int j = 0; j < 4; j++)
                    acc[i][j] = fmaf(ar[i], br[j], acc[i][j]);
        }
        #pragma unroll
        for (int i = 0; i < 4; i++) {
            float4 v = make_float4(acc[i][0]*0.125f, acc[i][1]*0.125f,
                                   acc[i][2]*0.125f, acc[i][3]*0.125f);
            *(float4*)&sS[(ty*4+i)*1024 + m0 + tx*4] = v;
        }
    }
    __syncthreads();

    int lane = t & 31, w = t >> 5;
    for (int rr = 0; rr < 4; rr++) {
        int i = w + rr*8;
        int r = n0 + i;
        if (r >= RN_) continue;
        int norig = ROWSEL[b*RN_ + r] - b*1024;
        float* row = sS + i*1024;
        float mx = -3.4e38f;
        for (int m = lane; m < 1024; m += 32) mx = fmaxf(mx, row[m]);
        #pragma unroll
        for (int o = 16; o; o >>= 1) mx = fmaxf(mx, __shfl_xor_sync(~0u, mx, o));
        const float* mrow = amask + (size_t)(b * N_ + norig) * N_;
        float sum = 0.f;
        for (int m = lane; m < 1024; m += 32) {
            float e = expf(row[m] - mx) * mrow[m];
            row[m] = e;
            sum += e;
        }
        #pragma unroll
        for (int o = 16; o; o >>= 1) sum += __shfl_xor_sync(~0u, sum, o);
        float rinv = 1.0f / (sum + 1e-6f);
        const float epsn = 1e-6f / 1024.0f;
        for (int m = lane; m < 1024; m += 32) row[m] = (row[m] + epsn) * rinv;
    }
    __syncthreads();

    float oacc[4][2] = {{0.f}};
    for (int vt = 0; vt < 8; vt++) {
        int m0 = vt << 7;
        __syncthreads();
        for (int e = t; e < 128*64; e += 256) {
            int m = e >> 6, d = e & 63;
            sT[m*66 + d] = QKV[base_bh + 1536 + (size_t)(m0 + m) * 2304 + d];
        }
        __syncthreads();
        #pragma unroll 4
        for (int m = 0; m < 128; m++) {
            float2 vv = *(const float2*)&sT[m*66 + tx*2];
            #pragma unroll
            for (int i = 0; i < 4; i++) {
                float a = sS[(ty*4+i)*1024 + m0 + m];
                oacc[i][0] = fmaf(a, vv.x, oacc[i][0]);
                oacc[i][1] = fmaf(a, vv.y, oacc[i][1]);
            }
        }
    }
    #pragma unroll
    for (int i = 0; i < 4; i++) {
        int r = n0 + ty*4 + i;
        if (r < RN_) {
            float2 o2 = make_float2(oacc[i][0], oacc[i][1]);
            *(float2*)&XATT[(size_t)(b*RN_ + r) * C_ + h*64 + tx*2] = o2;
        }
    }
}

// ---------------- top-k via bitonic sort (jax.lax.top_k semantics) ----------
__global__ __launch_bounds__(256) void topk_kernel(
    const float* __restrict__ CLSH, int* __restrict__ ROWSEL,
    float* __restrict__ outIA, float* __restrict__ outIM)
{
    __shared__ float sv[1024];
    __shared__ int   si[1024];
    int seg = blockIdx.x, b = blockIdx.y, t = threadIdx.x;
    int P     = seg ? 1024 : 256;
    int count = seg ? 768  : 255;
    int base  = seg ? 255  : 0;

    for (int e = t; e < P; e += 256) {
        if (e < count) {
            float s = 0.f;
            #pragma unroll
            for (int hh = 0; hh < 12; hh++)
                s += CLSH[(size_t)(b*12 + hh) * 1023 + base + e];
            sv[e] = s;
            si[e] = e;
        } else { sv[e] = -3.4e38f; si[e] = 0x7FFFFFFF; }
    }

    for (int k = 2; k <= P; k <<= 1)
        for (int j = k >> 1; j > 0; j >>= 1) {
            __syncthreads();
            for (int i = t; i < P; i += 256) {
                int ixj = i ^ j;
                if (ixj > i) {
                    float v1 = sv[i], v2 = sv[ixj];
                    int a1 = si[i], a2 = si[ixj];
                    bool before12 = (v1 > v2) || (v1 == v2 && a1 < a2);
                    bool up = ((i & k) == 0);
                    if (up != before12) {
                        sv[i] = v2; sv[ixj] = v1; si[i] = a2; si[ixj] = a1;
                    }
                }
            }
        }
    __syncthreads();

    if (seg == 0) {
        if (t < 128) {
            int idx = si[t];
            if (outIA) outIA[b*128 + t] = (float)idx;
            ROWSEL[b*513 + 1 + t] = b*1024 + 1 + idx;
        }
        if (t == 0) ROWSEL[b*513] = b*1024;
    } else {
        for (int e = t; e < 384; e += 256) {
            int idx = si[e];
            if (outIM) outIM[b*384 + e] = (float)idx;
            ROWSEL[b*513 + 129 + e] = b*1024 + 256 + idx;
        }
    }
}

__global__ void fill_ones(float* __restrict__ p, int n) {
    int i = blockIdx.x * 256 + threadIdx.x;
    if (i < n) p[i] = 1.0f;
}

// ---------------- launcher ----------------
extern "C" void kernel_launch(void* const* d_in, const int* in_sizes, int n_in,
                              void* d_out, int out_size)
{
    const float* x      = (const float*)d_in[0];
    const float* amask  = (const float*)d_in[1];
    const float* w_qkv  = (const float*)d_in[4];
    const float* w_proj = (const float*)d_in[5];
    const float* b_proj = (const float*)d_in[6];
    const float* g1     = (const float*)d_in[7];
    const float* b1     = (const float*)d_in[8];
    const float* g2     = (const float*)d_in[9];
    const float* b2     = (const float*)d_in[10];
    const float* w_fc1  = (const float*)d_in[11];
    const float* b_fc1  = (const float*)d_in[12];
    const float* w_fc2  = (const float*)d_in[13];
    const float* b_fc2  = (const float*)d_in[14];
    float* out = (float*)d_out;

    float *XN, *QKV, *QG, *XATT, *CLSH, *XP, *XN2, *HB; int* ROWSEL;
    cudaGetSymbolAddress((void**)&XN,   g_XN);
    cudaGetSymbolAddress((void**)&QKV,  g_QKV);
    cudaGetSymbolAddress((void**)&QG,   g_QG);
    cudaGetSymbolAddress((void**)&XATT, g_XATT);
    cudaGetSymbolAddress((void**)&CLSH, g_CLSH);
    cudaGetSymbolAddress((void**)&XP,   g_XP);
    cudaGetSymbolAddress((void**)&XN2,  g_XN2);
    cudaGetSymbolAddress((void**)&HB,   g_HB);
    cudaGetSymbolAddress((void**)&ROWSEL, g_ROWSEL);

    const int ATTN_SMEM = (32*1024 + 64*36 + 8448) * 4;  // 174080 B
    cudaFuncSetAttribute(attn_sel_kernel,
        cudaFuncAttributeMaxDynamicSharedMemorySize, ATTN_SMEM);

    const int OFF_IA = 8*513*768;
    const int OFF_IM = OFF_IA + 8*128;
    const int OFF_MK = OFF_IM + 8*384;
    const int MK_SZ  = 8*513*513;
    const int TOTAL  = OFF_MK + MK_SZ;
    float* outIA = (out_size >= TOTAL) ? out + OFF_IA : nullptr;
    float* outIM = (out_size >= TOTAL) ? out + OFF_IM : nullptr;

    // 1. LN1 (all rows)
    ln_kernel<<<B_*N_, 256>>>(x, g1, b1, XN);
    // 2a. K GEMM (fp32 EXACT — feeds cls scores -> top-k). Same column-block
    //     decomposition as R10 => bit-identical K.
    sgemm2<false><<<dim3(6, 64), 256>>>(
        XN, C_, w_qkv + 768, 3*C_, QKV + 768, 3*C_, B_*N_, C_, C_, nullptr);
    // 2b. V GEMM (bf16x3 mma — feeds AV only, tolerant)
    bf_gemm<false,false,0><<<dim3(6, 64), 256>>>(
        XN, C_, w_qkv + 1536, 3*C_, QKV + 1536, 3*C_, B_*N_, C_, C_,
        nullptr, nullptr, nullptr);
    // 3. cls attention row (fp32) -> CLSH
    cls_kernel<<<dim3(H_, B_), 256>>>(XN, w_qkv, QKV, amask, CLSH);
    // 4. top-k -> ROWSEL + idx outputs
    topk_kernel<<<dim3(2, B_), 256>>>(CLSH, ROWSEL, outIA, outIM);
    // 5. gathered Q GEMM (bf16x3): QG = XN[sel] @ w_qkv[:,0:768]
    bf_gemm<true,false,0><<<dim3(6, 33), 256>>>(
        XN, C_, w_qkv, 3*C_, QG, C_, MROWS, C_, C_, nullptr, nullptr, ROWSEL);
    // 6. attention for selected rows only (fp32 SIMT)
    attn_sel_kernel<<<dim3((RN_+31)/32, H_, B_), 256, ATTN_SMEM>>>(
        QG, QKV, amask, ROWSEL, XATT);
    // 7. proj (bf16x3): XP = x[sel] + (XATT @ w_proj + b_proj)
    bf_gemm<false,true,1><<<dim3(6, 33), 256>>>(
        XATT, C_, w_proj, C_, XP, C_, MROWS, C_, C_, b_proj, x, ROWSEL);
    // 8. LN2
    ln_kernel<<<MROWS, 256>>>(XP, g2, b2, XN2);
    // 9. fc1 + GELU (bf16x3)
    bf_gemm<false,false,2><<<dim3(24, 33), 256>>>(
        XN2, C_, w_fc1, HID_, HB, HID_, MROWS, HID_, C_, b_fc1, nullptr, nullptr);
    // 10. fc2 + bias + residual -> d_out (bf16x3)
    bf_gemm<false,false,1><<<dim3(6, 33), 256>>>(
        HB, HID_, w_fc2, C_, out, C_, MROWS, C_, HID_, b_fc2, XP, nullptr);
    // 11. new_mask == all ones (proved in R4)
    if (out_size >= TOTAL)
        fill_ones<<<(MK_SZ + 255)/256, 256>>>(out + OFF_MK, MK_SZ);
}

// round 13
// speedup vs baseline: 1.8062x; 1.0006x over previous
#include <cuda_runtime.h>
#include <cuda_bf16.h>
#include <cstdint>
#include <math.h>

#define B_   8
#define N_   1024
#define C_   768
#define H_   12
#define HID_ 3072
#define RN_  513
#define MROWS (B_*RN_)   // 4104

// ---------------- scratch (static __device__, no allocation) ----------------
__device__ float g_XN  [B_*N_*C_];
__device__ float g_QKV [B_*N_*3*C_];   // K,V region (cols 768..2303) used
__device__ float g_QG  [MROWS*C_];
__device__ float g_XATT[MROWS*C_];
__device__ float g_CLSH[B_*H_*(N_-1)];
__device__ int   g_ROWSEL[B_*RN_];
__device__ float g_XP  [MROWS*C_];
__device__ float g_XN2 [MROWS*C_];
__device__ float g_HB  [MROWS*HID_];

__device__ __forceinline__ float gelu_exact(float v) {
    return 0.5f * v * (1.0f + erff(v * 0.70710678118654752f));
}

// ---------------- LayerNorm (1 row / block, C=768, 256 threads) -------------
__global__ __launch_bounds__(256) void ln_kernel(
    const float* __restrict__ X, const float* __restrict__ g,
    const float* __restrict__ bt, float* __restrict__ Y)
{
    __shared__ float red[8];
    int row = blockIdx.x, t = threadIdx.x;
    const float* xr = X + (size_t)row * C_;
    float x0 = xr[t], x1 = xr[t+256], x2 = xr[t+512];
    float s = x0 + x1 + x2;
    #pragma unroll
    for (int o = 16; o; o >>= 1) s += __shfl_xor_sync(~0u, s, o);
    if ((t & 31) == 0) red[t >> 5] = s;
    __syncthreads();
    float tot = 0.f;
    #pragma unroll
    for (int i = 0; i < 8; i++) tot += red[i];
    float mean = tot * (1.0f/768.0f);
    __syncthreads();
    float d0 = x0-mean, d1 = x1-mean, d2 = x2-mean;
    float q = d0*d0 + d1*d1 + d2*d2;
    #pragma unroll
    for (int o = 16; o; o >>= 1) q += __shfl_xor_sync(~0u, q, o);
    if ((t & 31) == 0) red[t >> 5] = q;
    __syncthreads();
    float tq = 0.f;
    #pragma unroll
    for (int i = 0; i < 8; i++) tq += red[i];
    float rstd = 1.0f / sqrtf(tq * (1.0f/768.0f) + 1e-5f);
    float* yr = Y + (size_t)row * C_;
    yr[t]     = d0*rstd*g[t]     + bt[t];
    yr[t+256] = d1*rstd*g[t+256] + bt[t+256];
    yr[t+512] = d2*rstd*g[t+512] + bt[t+512];
}

// ------- fp32 SGEMM w/ strides (exact path for K): 128x128x8, 8x8 ----------
template<bool GATHER>
__global__ __launch_bounds__(256) void sgemm2(
    const float* __restrict__ A, int lda,
    const float* __restrict__ Bm, int ldb,
    float* __restrict__ Cm, int ldc,
    int M, int N, int K, const int* __restrict__ rowmap)
{
    __shared__ float As[8][128];
    __shared__ float Bs[8][128];
    int t = threadIdx.x;
    int row0 = blockIdx.y * 128, col0 = blockIdx.x * 128;

    int la_r = t >> 1, la_k = (t & 1) * 4;
    long a_base = -1;
    {
        int arow = row0 + la_r;
        if (arow < M) a_base = (long)(GATHER ? rowmap[arow] : arow) * lda;
    }
    int lb_k = t >> 5, lb_c = (t & 31) * 4;
    const float* bp = Bm + (size_t)lb_k * ldb + col0 + lb_c;

    int ty = t >> 4, tx = t & 15;
    float acc[8][8] = {{0.f}};

    float4 av = make_float4(0.f,0.f,0.f,0.f), bv;
    if (a_base >= 0) av = *(const float4*)(A + a_base + la_k);
    bv = *(const float4*)bp;

    for (int k0 = 0; k0 < K; k0 += 8) {
        __syncthreads();
        As[la_k  ][la_r] = av.x;  As[la_k+1][la_r] = av.y;
        As[la_k+2][la_r] = av.z;  As[la_k+3][la_r] = av.w;
        *(float4*)&Bs[lb_k][lb_c] = bv;
        __syncthreads();
        if (k0 + 8 < K) {
            if (a_base >= 0) av = *(const float4*)(A + a_base + k0 + 8 + la_k);
            bv = *(const float4*)(bp + (size_t)(k0 + 8) * ldb);
        }
        #pragma unroll
        for (int kk = 0; kk < 8; kk++) {
            float4 a0 = *(const float4*)&As[kk][ty*8];
            float4 a1 = *(const float4*)&As[kk][ty*8+4];
            float4 b0 = *(const float4*)&Bs[kk][tx*8];
            float4 b1 = *(const float4*)&Bs[kk][tx*8+4];
            float ar[8] = {a0.x,a0.y,a0.z,a0.w,a1.x,a1.y,a1.z,a1.w};
            float br[8] = {b0.x,b0.y,b0.z,b0.w,b1.x,b1.y,b1.z,b1.w};
            #pragma unroll
            for (int i = 0; i < 8; i++)
                #pragma unroll
                for (int j = 0; j < 8; j++)
                    acc[i][j] = fmaf(ar[i], br[j], acc[i][j]);
        }
    }

    #pragma unroll
    for (int i = 0; i < 8; i++) {
        int row = row0 + ty*8 + i;
        if (row < M) {
            #pragma unroll
            for (int jj = 0; jj < 8; jj += 4) {
                int col = col0 + tx*8 + jj;
                float4 v = make_float4(acc[i][jj], acc[i][jj+1], acc[i][jj+2], acc[i][jj+3]);
                *(float4*)&Cm[(size_t)row * ldc + col] = v;
            }
        }
    }
}

// ============ bf16x3 MMA GEMM (m16n8k16 + ldmatrix), 128x128, BK=32 =========
// 8 warps 2(M)x4(N), warp tile 64x32. Error ~2^-17 (post-topk path only).
// EPI: 0 plain, 1 +bias+resid, 2 +bias+GELU. GA: gather A rows; GR: gather resid.
#define LDSM_X4(r0,r1,r2,r3,addr) \
    asm volatile("ldmatrix.sync.aligned.m8n8.x4.shared.b16 {%0,%1,%2,%3},[%4];" \
        : "=r"(r0),"=r"(r1),"=r"(r2),"=r"(r3) : "r"(addr))
#define LDSM_X4T(r0,r1,r2,r3,addr) \
    asm volatile("ldmatrix.sync.aligned.m8n8.x4.trans.shared.b16 {%0,%1,%2,%3},[%4];" \
        : "=r"(r0),"=r"(r1),"=r"(r2),"=r"(r3) : "r"(addr))

__device__ __forceinline__ void mma_bf16(float* c, const uint32_t* a,
                                         uint32_t b0, uint32_t b1) {
    asm volatile(
        "mma.sync.aligned.m16n8k16.row.col.f32.bf16.bf16.f32 "
        "{%0,%1,%2,%3},{%4,%5,%6,%7},{%8,%9},{%0,%1,%2,%3};"
        : "+f"(c[0]), "+f"(c[1]), "+f"(c[2]), "+f"(c[3])
        : "r"(a[0]), "r"(a[1]), "r"(a[2]), "r"(a[3]), "r"(b0), "r"(b1));
}

__device__ __forceinline__ void cvt16(const float* v, uint32_t* uh, uint32_t* ul) {
    #pragma unroll
    for (int p = 0; p < 8; p++) {
        float a = v[2*p], b = v[2*p+1];
        __nv_bfloat16 ha = __float2bfloat16(a), hb = __float2bfloat16(b);
        __nv_bfloat162 hi2; hi2.x = ha; hi2.y = hb;
        __nv_bfloat162 lo2 = __floats2bfloat162_rn(
            a - __bfloat162float(ha), b - __bfloat162float(hb));
        uh[p] = *(uint32_t*)&hi2;
        ul[p] = *(uint32_t*)&lo2;
    }
}

// smem: A rows 128, stride 80B (64B data + 16 pad); B rows 32 (k), stride 272B
#define A_STR 80
#define B_STR 272

template<bool GA, bool GR, int EPI>
__global__ __launch_bounds__(256) void bf_gemm(
    const float* __restrict__ A, int lda,
    const float* __restrict__ Bm, int ldb,
    float* __restrict__ Cm, int ldc,
    int M, int N, int K,
    const float* __restrict__ bias, const float* __restrict__ resid,
    const int* __restrict__ rowmap)
{
    __shared__ __align__(16) char sAh[128*A_STR];
    __shared__ __align__(16) char sAl[128*A_STR];
    __shared__ __align__(16) char sBh[32*B_STR];
    __shared__ __align__(16) char sBl[32*B_STR];

    const int t = threadIdx.x;
    const int lane = t & 31, wid = t >> 5;
    const int lq = lane >> 2, lr = lane & 3;
    const int wm = wid & 1,  wn = wid >> 1;
    const int row0 = blockIdx.y * 128, col0 = blockIdx.x * 128;

    // ---- loader mapping
    const int la_r = t >> 1, la_half = (t & 1);       // A: row, k-half(16)
    const int lb_k = t >> 3, lb_n = (t & 7) * 16;     // B: k-row, n-offset
    long a_base = -1;
    {
        int arow = row0 + la_r;
        if (arow < M) a_base = (long)(GA ? rowmap[arow] : arow) * lda;
    }
    const float* bptr = Bm + (size_t)lb_k * ldb + col0 + lb_n;

    // ---- ldmatrix per-thread addresses
    uint32_t a_h_base, a_l_base, b_h_base, b_l_base;
    {
        uint32_t sa;
        asm("{ .reg .u64 tt; cvta.to.shared.u64 tt, %1; cvt.u32.u64 %0, tt; }"
            : "=r"(sa) : "l"((void*)sAh));
        uint32_t arow = wm*64 + ((lane>>3)&1)*8 + (lane&7);
        uint32_t aoff = arow*A_STR + (lane>>4)*16;
        a_h_base = sa + aoff;
        asm("{ .reg .u64 tt; cvta.to.shared.u64 tt, %1; cvt.u32.u64 %0, tt; }"
            : "=r"(sa) : "l"((void*)sAl));
        a_l_base = sa + aoff;
        uint32_t brow = ((lane>>3)&1)*8 + (lane&7);
        uint32_t boff = brow*B_STR + wn*64 + (lane>>4)*16;
        asm("{ .reg .u64 tt; cvta.to.shared.u64 tt, %1; cvt.u32.u64 %0, tt; }"
            : "=r"(sa) : "l"((void*)sBh));
        b_h_base = sa + boff;
        asm("{ .reg .u64 tt; cvta.to.shared.u64 tt, %1; cvt.u32.u64 %0, tt; }"
            : "=r"(sa) : "l"((void*)sBl));
        b_l_base = sa + boff;
    }

    float acc[4][4][4];
    #pragma unroll
    for (int i = 0; i < 4; i++)
        #pragma unroll
        for (int j = 0; j < 4; j++)
            #pragma unroll
            for (int q = 0; q < 4; q++) acc[i][j][q] = 0.f;

    float av[16], bv[16];
    auto ldg = [&](int kt) {
        int k0 = kt * 32 + la_half * 16;
        if (a_base >= 0) {
            #pragma unroll
            for (int j = 0; j < 4; j++)
                *(float4*)&av[j*4] = *(const float4*)(A + a_base + k0 + j*4);
        } else {
            #pragma unroll
            for (int j = 0; j < 16; j++) av[j] = 0.f;
        }
        const float* bp = bptr + (size_t)(kt*32) * ldb;
        #pragma unroll
        for (int j = 0; j < 4; j++)
            *(float4*)&bv[j*4] = *(const float4*)(bp + j*4);
    };

    const int KT = K >> 5;
    ldg(0);

    for (int kt = 0; kt < KT; ++kt) {
        // store current tile (hi/lo split) to smem
        {
            uint32_t uh[8], ul[8];
            cvt16(av, uh, ul);
            char* pa = sAh + la_r*A_STR + la_half*32;
            *(uint4*)pa        = make_uint4(uh[0],uh[1],uh[2],uh[3]);
            *(uint4*)(pa + 16) = make_uint4(uh[4],uh[5],uh[6],uh[7]);
            pa = sAl + la_r*A_STR + la_half*32;
            *(uint4*)pa        = make_uint4(ul[0],ul[1],ul[2],ul[3]);
            *(uint4*)(pa + 16) = make_uint4(ul[4],ul[5],ul[6],ul[7]);
            cvt16(bv, uh, ul);
            char* pb = sBh + lb_k*B_STR + lb_n*2;
            *(uint4*)pb        = make_uint4(uh[0],uh[1],uh[2],uh[3]);
            *(uint4*)(pb + 16) = make_uint4(uh[4],uh[5],uh[6],uh[7]);
            pb = sBl + lb_k*B_STR + lb_n*2;
            *(uint4*)pb        = make_uint4(ul[0],ul[1],ul[2],ul[3]);
            *(uint4*)(pb + 16) = make_uint4(ul[4],ul[5],ul[6],ul[7]);
        }
        __syncthreads();
        if (kt + 1 < KT) ldg(kt + 1);

        #pragma unroll
        for (int ks = 0; ks < 2; ks++) {
            uint32_t ah[4][4], al_[4][4], bh[4][2], bl_[4][2];
            #pragma unroll
            for (int mf = 0; mf < 4; mf++) {
                uint32_t aa = a_h_base + mf*(16*A_STR) + ks*32;
                LDSM_X4(ah[mf][0],ah[mf][1],ah[mf][2],ah[mf][3], aa);
                aa = a_l_base + mf*(16*A_STR) + ks*32;
                LDSM_X4(al_[mf][0],al_[mf][1],al_[mf][2],al_[mf][3], aa);
            }
            #pragma unroll
            for (int nfp = 0; nfp < 2; nfp++) {
                uint32_t bb = b_h_base + ks*(16*B_STR) + nfp*32;
                LDSM_X4T(bh[2*nfp][0], bh[2*nfp][1], bh[2*nfp+1][0], bh[2*nfp+1][1], bb);
                bb = b_l_base + ks*(16*B_STR) + nfp*32;
                LDSM_X4T(bl_[2*nfp][0], bl_[2*nfp][1], bl_[2*nfp+1][0], bl_[2*nfp+1][1], bb);
            }
            #pragma unroll
            for (int mf = 0; mf < 4; mf++)
                #pragma unroll
                for (int nf = 0; nf < 4; nf++) {
                    float* c = acc[mf][nf];
                    mma_bf16(c, ah[mf],  bh[nf][0],  bh[nf][1]);
                    mma_bf16(c, ah[mf],  bl_[nf][0], bl_[nf][1]);
                    mma_bf16(c, al_[mf], bh[nf][0],  bh[nf][1]);
                }
        }
        __syncthreads();
    }

    // ---- epilogue (same fragment layout as m16n8 tf32 version)
    #pragma unroll
    for (int mf = 0; mf < 4; mf++) {
        int rbase = row0 + wm*64 + mf*16 + lq;
        #pragma unroll
        for (int half = 0; half < 2; half++) {
            int row = rbase + half*8;
            if (row < M) {
                long rres = 0;
                if (EPI == 1) rres = (long)(GR ? rowmap[row] : row) * N;
                #pragma unroll
                for (int nf = 0; nf < 4; nf++) {
                    int col = col0 + wn*32 + nf*8 + lr*2;
                    float v0 = acc[mf][nf][half*2+0];
                    float v1 = acc[mf][nf][half*2+1];
                    if (EPI != 0) { v0 += bias[col]; v1 += bias[col+1]; }
                    if (EPI == 2) { v0 = gelu_exact(v0); v1 = gelu_exact(v1); }
                    if (EPI == 1) { v0 += resid[rres+col]; v1 += resid[rres+col+1]; }
                    *(float2*)&Cm[(size_t)row * ldc + col] = make_float2(v0, v1);
                }
            }
        }
    }
}

// ------------- cls attention row (q0 = xn0 @ Wq, softmax, -> CLSH) ----------
__global__ __launch_bounds__(256) void cls_kernel(
    const float* __restrict__ XN, const float* __restrict__ wqkv,
    const float* __restrict__ QKV, const float* __restrict__ amask,
    float* __restrict__ CLSH)
{
    __shared__ float q0[64];
    __shared__ float sS[1024];
    __shared__ float red[8];
    int h = blockIdx.x, b = blockIdx.y, t = threadIdx.x;

    {
        int d = t >> 2, part = t & 3;
        const float* xr = XN + (size_t)b * N_ * C_;
        const float* wc = wqkv + h*64 + d;
        float s = 0.f;
        int k0 = part * 192;
        for (int k = k0; k < k0 + 192; k++)
            s = fmaf(xr[k], wc[(size_t)k * 2304], s);
        s += __shfl_xor_sync(~0u, s, 1);
        s += __shfl_xor_sync(~0u, s, 2);
        if (part == 0) q0[d] = s;
    }
    __syncthreads();

    float sv[4];
    #pragma unroll
    for (int j = 0; j < 4; j++) {
        int m = t + 256*j;
        const float* kr = QKV + (size_t)(b*N_ + m)*2304 + 768 + h*64;
        float acc = 0.f;
        #pragma unroll
        for (int d = 0; d < 64; d++) acc = fmaf(q0[d], kr[d], acc);
        sv[j] = acc * 0.125f;
    }
    float mx = fmaxf(fmaxf(sv[0], sv[1]), fmaxf(sv[2], sv[3]));
    #pragma unroll
    for (int o = 16; o; o >>= 1) mx = fmaxf(mx, __shfl_xor_sync(~0u, mx, o));
    if ((t & 31) == 0) red[t >> 5] = mx;
    __syncthreads();
    mx = red[0];
    #pragma unroll
    for (int i = 1; i < 8; i++) mx = fmaxf(mx, red[i]);

    const float* mrow = amask + (size_t)b * N_ * N_;
    float sum = 0.f;
    #pragma unroll
    for (int j = 0; j < 4; j++) {
        int m = t + 256*j;
        float e = expf(sv[j] - mx) * mrow[m];
        sS[m] = e;
        sum += e;
    }
    #pragma unroll
    for (int o = 16; o; o >>= 1) sum += __shfl_xor_sync(~0u, sum, o);
    __syncthreads();
    if ((t & 31) == 0) red[t >> 5] = sum;
    __syncthreads();
    sum = 0.f;
    #pragma unroll
    for (int i = 0; i < 8; i++) sum += red[i];
    float rinv = 1.0f / (sum + 1e-6f);
    const float epsn = 1e-6f / 1024.0f;
    float* cl = CLSH + (size_t)(b*H_ + h) * (N_ - 1);
    #pragma unroll
    for (int j = 0; j < 4; j++) {
        int m = t + 256*j;
        if (m >= 1) cl[m-1] = (sS[m] + epsn) * rinv;
    }
}

// --------- Attention for SELECTED rows: block = (32 compact rows, h, b) -----
__global__ __launch_bounds__(256) void attn_sel_kernel(
    const float* __restrict__ QG, const float* __restrict__ QKV,
    const float* __restrict__ amask, const int* __restrict__ ROWSEL,
    float* __restrict__ XATT)
{
    extern __shared__ float smx[];
    float* sS  = smx;                 // 32*1024
    float* sQt = smx + 32*1024;       // [64][36]
    float* sT  = sQt + 64*36;         // 8448 floats
    int t = threadIdx.x;
    int n0 = blockIdx.x * 32, h = blockIdx.y, b = blockIdx.z;
    size_t base_bh = (size_t)b * N_ * 2304 + (size_t)h * 64;

    for (int e = t; e < 32*64; e += 256) {
        int i = e >> 6, d = e & 63;
        int r = n0 + i;
        sQt[d*36 + i] = (r < RN_)
            ? QG[(size_t)(b*RN_ + r) * C_ + h*64 + d] : 0.f;
    }

    int ty = t >> 5, tx = t & 31;

    for (int kt = 0; kt < 8; kt++) {
        int m0 = kt << 7;
        __syncthreads();
        for (int e = t; e < 128*64; e += 256) {
            int m = e >> 6, d = e & 63;
            sT[d*132 + m] = QKV[base_bh + 768 + (size_t)(m0 + m) * 2304 + d];
        }
        __syncthreads();
        float acc[4][4] = {{0.f}};
        #pragma unroll 4
        for (int d = 0; d < 64; d++) {
            float4 aq = *(const float4*)&sQt[d*36 + ty*4];
            float4 bk = *(const float4*)&sT[d*132 + tx*4];
            float ar[4] = {aq.x,aq.y,aq.z,aq.w};
            float br[4] = {bk.x,bk.y,bk.z,bk.w};
            #pragma unroll
            for (int i = 0; i < 4; i++)
                #pragma unroll
                for (int j = 0; j < 4; j++)
                    acc[i][j] = fmaf(ar[i], br[j], acc[i][j]);
        }
        #pragma unroll
        for (int i = 0; i < 4; i++) {
            float4 v = make_float4(acc[i][0]*0.125f, acc[i][1]*0.125f,
                                   acc[i][2]*0.125f, acc[i][3]*0.125f);
            *(float4*)&sS[(ty*4+i)*1024 + m0 + tx*4] = v;
        }
    }
    __syncthreads();

    int lane = t & 31, w = t >> 5;
    for (int rr = 0; rr < 4; rr++) {
        int i = w + rr*8;
        int r = n0 + i;
        if (r >= RN_) continue;
        int norig = ROWSEL[b*RN_ + r] - b*1024;
        float* row = sS + i*1024;
        float mx = -3.4e38f;
        for (int m = lane; m < 1024; m += 32) mx = fmaxf(mx, row[m]);
        #pragma unroll
        for (int o = 16; o; o >>= 1) mx = fmaxf(mx, __shfl_xor_sync(~0u, mx, o));
        const float* mrow = amask + (size_t)(b * N_ + norig) * N_;
        float sum = 0.f;
        for (int m = lane; m < 1024; m += 32) {
            float e = expf(row[m] - mx) * mrow[m];
            row[m] = e;
            sum += e;
        }
        #pragma unroll
        for (int o = 16; o; o >>= 1) sum += __shfl_xor_sync(~0u, sum, o);
        float rinv = 1.0f / (sum + 1e-6f);
        const float epsn = 1e-6f / 1024.0f;
        for (int m = lane; m < 1024; m += 32) row[m] = (row[m] + epsn) * rinv;
    }
    __syncthreads();

    float oacc[4][2] = {{0.f}};
    for (int vt = 0; vt < 8; vt++) {
        int m0 = vt << 7;
        __syncthreads();
        for (int e = t; e < 128*64; e += 256) {
            int m = e >> 6, d = e & 63;
            sT[m*66 + d] = QKV[base_bh + 1536 + (size_t)(m0 + m) * 2304 + d];
        }
        __syncthreads();
        #pragma unroll 4
        for (int m = 0; m < 128; m++) {
            float2 vv = *(const float2*)&sT[m*66 + tx*2];
            #pragma unroll
            for (int i = 0; i < 4; i++) {
                float a = sS[(ty*4+i)*1024 + m0 + m];
                oacc[i][0] = fmaf(a, vv.x, oacc[i][0]);
                oacc[i][1] = fmaf(a, vv.y, oacc[i][1]);
            }
        }
    }
    #pragma unroll
    for (int i = 0; i < 4; i++) {
        int r = n0 + ty*4 + i;
        if (r < RN_) {
            float2 o2 = make_float2(oacc[i][0], oacc[i][1]);
            *(float2*)&XATT[(size_t)(b*RN_ + r) * C_ + h*64 + tx*2] = o2;
        }
    }
}

// ---------------- top-k via bitonic sort (jax.lax.top_k semantics) ----------
__global__ __launch_bounds__(256) void topk_kernel(
    const float* __restrict__ CLSH, int* __restrict__ ROWSEL,
    float* __restrict__ outIA, float* __restrict__ outIM)
{
    __shared__ float sv[1024];
    __shared__ int   si[1024];
    int seg = blockIdx.x, b = blockIdx.y, t = threadIdx.x;
    int P     = seg ? 1024 : 256;
    int count = seg ? 768  : 255;
    int base  = seg ? 255  : 0;

    for (int e = t; e < P; e += 256) {
        if (e < count) {
            float s = 0.f;
            #pragma unroll
            for (int hh = 0; hh < 12; hh++)
                s += CLSH[(size_t)(b*12 + hh) * 1023 + base + e];
            sv[e] = s;
            si[e] = e;
        } else { sv[e] = -3.4e38f; si[e] = 0x7FFFFFFF; }
    }

    for (int k = 2; k <= P; k <<= 1)
        for (int j = k >> 1; j > 0; j >>= 1) {
            __syncthreads();
            for (int i = t; i < P; i += 256) {
                int ixj = i ^ j;
                if (ixj > i) {
                    float v1 = sv[i], v2 = sv[ixj];
                    int a1 = si[i], a2 = si[ixj];
                    bool before12 = (v1 > v2) || (v1 == v2 && a1 < a2);
                    bool up = ((i & k) == 0);
                    if (up != before12) {
                        sv[i] = v2; sv[ixj] = v1; si[i] = a2; si[ixj] = a1;
                    }
                }
            }
        }
    __syncthreads();

    if (seg == 0) {
        if (t < 128) {
            int idx = si[t];
            if (outIA) outIA[b*128 + t] = (float)idx;
            ROWSEL[b*513 + 1 + t] = b*1024 + 1 + idx;
        }
        if (t == 0) ROWSEL[b*513] = b*1024;
    } else {
        for (int e = t; e < 384; e += 256) {
            int idx = si[e];
            if (outIM) outIM[b*384 + e] = (float)idx;
            ROWSEL[b*513 + 129 + e] = b*1024 + 256 + idx;
        }
    }
}

__global__ void fill_ones(float* __restrict__ p, int n) {
    int i = blockIdx.x * 256 + threadIdx.x;
    if (i < n) p[i] = 1.0f;
}

// ---------------- launcher ----------------
extern "C" void kernel_launch(void* const* d_in, const int* in_sizes, int n_in,
                              void* d_out, int out_size)
{
    const float* x      = (const float*)d_in[0];
    const float* amask  = (const float*)d_in[1];
    const float* w_qkv  = (const float*)d_in[4];
    const float* w_proj = (const float*)d_in[5];
    const float* b_proj = (const float*)d_in[6];
    const float* g1     = (const float*)d_in[7];
    const float* b1     = (const float*)d_in[8];
    const float* g2     = (const float*)d_in[9];
    const float* b2     = (const float*)d_in[10];
    const float* w_fc1  = (const float*)d_in[11];
    const float* b_fc1  = (const float*)d_in[12];
    const float* w_fc2  = (const float*)d_in[13];
    const float* b_fc2  = (const float*)d_in[14];
    float* out = (float*)d_out;

    float *XN, *QKV, *QG, *XATT, *CLSH, *XP, *XN2, *HB; int* ROWSEL;
    cudaGetSymbolAddress((void**)&XN,   g_XN);
    cudaGetSymbolAddress((void**)&QKV,  g_QKV);
    cudaGetSymbolAddress((void**)&QG,   g_QG);
    cudaGetSymbolAddress((void**)&XATT, g_XATT);
    cudaGetSymbolAddress((void**)&CLSH, g_CLSH);
    cudaGetSymbolAddress((void**)&XP,   g_XP);
    cudaGetSymbolAddress((void**)&XN2,  g_XN2);
    cudaGetSymbolAddress((void**)&HB,   g_HB);
    cudaGetSymbolAddress((void**)&ROWSEL, g_ROWSEL);

    const int ATTN_SMEM = (32*1024 + 64*36 + 8448) * 4;  // 174080 B
    cudaFuncSetAttribute(attn_sel_kernel,
        cudaFuncAttributeMaxDynamicSharedMemorySize, ATTN_SMEM);

    const int OFF_IA = 8*513*768;
    const int OFF_IM = OFF_IA + 8*128;
    const int OFF_MK = OFF_IM + 8*384;
    const int MK_SZ  = 8*513*513;
    const int TOTAL  = OFF_MK + MK_SZ;
    float* outIA = (out_size >= TOTAL) ? out + OFF_IA : nullptr;
    float* outIM = (out_size >= TOTAL) ? out + OFF_IM : nullptr;

    // 1. LN1 (all rows)
    ln_kernel<<<B_*N_, 256>>>(x, g1, b1, XN);
    // 2a. K GEMM (fp32 EXACT — feeds cls scores -> top-k). Same column-block
    //     decomposition as R10 => bit-identical K.
    sgemm2<false><<<dim3(6, 64), 256>>>(
        XN, C_, w_qkv + 768, 3*C_, QKV + 768, 3*C_, B_*N_, C_, C_, nullptr);
    // 2b. V GEMM (bf16x3 mma — feeds AV only, tolerant)
    bf_gemm<false,false,0><<<dim3(6, 64), 256>>>(
        XN, C_, w_qkv + 1536, 3*C_, QKV + 1536, 3*C_, B_*N_, C_, C_,
        nullptr, nullptr, nullptr);
    // 3. cls attention row (fp32) -> CLSH
    cls_kernel<<<dim3(H_, B_), 256>>>(XN, w_qkv, QKV, amask, CLSH);
    // 4. top-k -> ROWSEL + idx outputs
    topk_kernel<<<dim3(2, B_), 256>>>(CLSH, ROWSEL, outIA, outIM);
    // 5. gathered Q GEMM (bf16x3): QG = XN[sel] @ w_qkv[:,0:768]
    bf_gemm<true,false,0><<<dim3(6, 33), 256>>>(
        XN, C_, w_qkv, 3*C_, QG, C_, MROWS, C_, C_, nullptr, nullptr, ROWSEL);
    // 6. attention for selected rows only (fp32 SIMT)
    attn_sel_kernel<<<dim3((RN_+31)/32, H_, B_), 256, ATTN_SMEM>>>(
        QG, QKV, amask, ROWSEL, XATT);
    // 7. proj (bf16x3): XP = x[sel] + (XATT @ w_proj + b_proj)
    bf_gemm<false,true,1><<<dim3(6, 33), 256>>>(
        XATT, C_, w_proj, C_, XP, C_, MROWS, C_, C_, b_proj, x, ROWSEL);
    // 8. LN2
    ln_kernel<<<MROWS, 256>>>(XP, g2, b2, XN2);
    // 9. fc1 + GELU (bf16x3)
    bf_gemm<false,false,2><<<dim3(24, 33), 256>>>(
        XN2, C_, w_fc1, HID_, HB, HID_, MROWS, HID_, C_, b_fc1, nullptr, nullptr);
    // 10. fc2 + bias + residual -> d_out (bf16x3)
    bf_gemm<false,false,1><<<dim3(6, 33), 256>>>(
        HB, HID_, w_fc2, C_, out, C_, MROWS, C_, HID_, b_fc2, XP, nullptr);
    // 11. new_mask == all ones (proved in R4)
    if (out_size >= TOTAL)
        fill_ones<<<(MK_SZ + 255)/256, 256>>>(out + OFF_MK, MK_SZ);
}